// round 2
// baseline (speedup 1.0000x reference)
#include <cuda_runtime.h>
#include <cuda_bf16.h>
#include <math.h>

#define BB 16
#define HH 56
#define WW 56
#define EMB 768
#define NH 12
#define DH 64
#define TOK (BB*HH*WW)          // 50176
#define SCALING 0.125f          // 64^-0.5
#define KSTEPS (EMB/16)         // 48

// ---------------- scratch (static device arrays; no allocation) ----------------
__device__ float g_q [(size_t)TOK * EMB];
__device__ float g_k [(size_t)TOK * EMB];
__device__ float g_v [(size_t)TOK * EMB];
__device__ float g_vw[(size_t)TOK * EMB];
__device__ float g_ao[(size_t)TOK * EMB];

__device__ __nv_bfloat16 g_xh [(size_t)TOK * EMB];
__device__ __nv_bfloat16 g_xl [(size_t)TOK * EMB];
__device__ __nv_bfloat16 g_aoh[(size_t)TOK * EMB];
__device__ __nv_bfloat16 g_aol[(size_t)TOK * EMB];
__device__ __nv_bfloat16 g_wh [(size_t)4 * EMB * EMB];   // Wq,Wk,Wv,Wo hi
__device__ __nv_bfloat16 g_wl [(size_t)4 * EMB * EMB];   // lo

// ---------------------------------------------------------------------------
// Split fp32 -> (hi, lo) bf16 pair:  x ~= hi + lo, residual ~ 2^-17 * |x|
// n must be a multiple of 4.
// ---------------------------------------------------------------------------
__global__ void split_f32_bf16(const float* __restrict__ s,
                               __nv_bfloat16* __restrict__ hi,
                               __nv_bfloat16* __restrict__ lo, int n)
{
    int i = (blockIdx.x * blockDim.x + threadIdx.x) * 4;
    if (i >= n) return;
    float4 v = *(const float4*)(s + i);
    __nv_bfloat16 h0 = __float2bfloat16_rn(v.x);
    __nv_bfloat16 h1 = __float2bfloat16_rn(v.y);
    __nv_bfloat16 h2 = __float2bfloat16_rn(v.z);
    __nv_bfloat16 h3 = __float2bfloat16_rn(v.w);
    __nv_bfloat16 l0 = __float2bfloat16_rn(v.x - __bfloat162float(h0));
    __nv_bfloat16 l1 = __float2bfloat16_rn(v.y - __bfloat162float(h1));
    __nv_bfloat16 l2 = __float2bfloat16_rn(v.z - __bfloat162float(h2));
    __nv_bfloat16 l3 = __float2bfloat16_rn(v.w - __bfloat162float(h3));
    *(__nv_bfloat162*)(hi + i)     = __nv_bfloat162(h0, h1);
    *(__nv_bfloat162*)(hi + i + 2) = __nv_bfloat162(h2, h3);
    *(__nv_bfloat162*)(lo + i)     = __nv_bfloat162(l0, l1);
    *(__nv_bfloat162*)(lo + i + 2) = __nv_bfloat162(l2, l3);
}

// ---------------------------------------------------------------------------
// Tensor-core GEMM with bf16 split compensation:
//   C[m,n] = scale * ( sum_k A[m,k]*B[n,k] + bias[n] ),  A ~ Ah+Al, B ~ Bh+Bl.
// Per fragment: acc += ah*bh + ah*bl + al*bh   (al*bl dropped, ~2^-34).
// Block 128x128, BK=16, 8 warps (4x2), warp tile 32x64, double-buffered SMEM.
// M%128==0, N%128==0, K%16==0 (true here).
// ---------------------------------------------------------------------------
#define SROW 24                     // smem row stride in bf16 (48B, conflict-free)
#define STG  (128*SROW)             // one tile (bf16 elems)

__device__ __forceinline__ unsigned smem_u32(const void* p) {
    return (unsigned)__cvta_generic_to_shared(p);
}
__device__ __forceinline__ void ldsm_x4(unsigned* r, unsigned addr) {
    asm volatile("ldmatrix.sync.aligned.m8n8.x4.shared.b16 {%0,%1,%2,%3}, [%4];"
                 : "=r"(r[0]), "=r"(r[1]), "=r"(r[2]), "=r"(r[3]) : "r"(addr));
}
__device__ __forceinline__ void ldsm_x2(unsigned* r, unsigned addr) {
    asm volatile("ldmatrix.sync.aligned.m8n8.x2.shared.b16 {%0,%1}, [%2];"
                 : "=r"(r[0]), "=r"(r[1]) : "r"(addr));
}
__device__ __forceinline__ void mma_bf16(float* c, const unsigned* a, const unsigned* b) {
    asm volatile("mma.sync.aligned.m16n8k16.row.col.f32.bf16.bf16.f32 "
                 "{%0,%1,%2,%3}, {%4,%5,%6,%7}, {%8,%9}, {%0,%1,%2,%3};"
                 : "+f"(c[0]), "+f"(c[1]), "+f"(c[2]), "+f"(c[3])
                 : "r"(a[0]), "r"(a[1]), "r"(a[2]), "r"(a[3]), "r"(b[0]), "r"(b[1]));
}

__global__ __launch_bounds__(256)
void gemm_mma_split(const __nv_bfloat16* __restrict__ Ah, const __nv_bfloat16* __restrict__ Al,
                    const __nv_bfloat16* __restrict__ Bh, const __nv_bfloat16* __restrict__ Bl,
                    const float* __restrict__ bias, float* __restrict__ C,
                    int M, int N, int K, float scale)
{
    extern __shared__ __align__(16) __nv_bfloat16 sm[];
    __nv_bfloat16* sAh = sm;                 // [2][STG]
    __nv_bfloat16* sAl = sm + 2*STG;
    __nv_bfloat16* sBh = sm + 4*STG;
    __nv_bfloat16* sBl = sm + 6*STG;

    const int tid  = threadIdx.x;
    const int lane = tid & 31;
    const int warp = tid >> 5;
    const int wm   = warp >> 1;              // 0..3
    const int wn   = warp & 1;               // 0..1
    const int m0   = blockIdx.y * 128;
    const int n0   = blockIdx.x * 128;

    // global->smem: thread loads one uint4 (8 bf16) per tile per stage
    const int lrow = tid >> 1;               // 0..127
    const int lhal = (tid & 1) * 8;          // 0 or 8 (k offset)
    const __nv_bfloat16* gAh = Ah + (size_t)(m0 + lrow) * K + lhal;
    const __nv_bfloat16* gAl = Al + (size_t)(m0 + lrow) * K + lhal;
    const __nv_bfloat16* gBh = Bh + (size_t)(n0 + lrow) * K + lhal;
    const __nv_bfloat16* gBl = Bl + (size_t)(n0 + lrow) * K + lhal;
    const int soff = lrow * SROW + lhal;     // smem store offset (bf16 units)

    float acc[2][8][4];
    #pragma unroll
    for (int mt = 0; mt < 2; mt++)
        #pragma unroll
        for (int nt = 0; nt < 8; nt++)
            #pragma unroll
            for (int r = 0; r < 4; r++) acc[mt][nt][r] = 0.0f;

    // fragment smem addresses (constant across k-steps, add buffer offset)
    unsigned aAh[2], aAl[2], aBh[8], aBl[8];
    #pragma unroll
    for (int mt = 0; mt < 2; mt++) {
        int row = wm*32 + mt*16 + (lane & 15);
        int col = (lane >> 4) * 8;
        aAh[mt] = smem_u32(sAh + row*SROW + col);
        aAl[mt] = smem_u32(sAl + row*SROW + col);
    }
    #pragma unroll
    for (int nt = 0; nt < 8; nt++) {
        int row = wn*64 + nt*8 + (lane & 7);
        int col = ((lane >> 3) & 1) * 8;
        aBh[nt] = smem_u32(sBh + row*SROW + col);
        aBl[nt] = smem_u32(sBl + row*SROW + col);
    }

    // prologue: stage 0
    {
        uint4 vah = *(const uint4*)gAh;
        uint4 val = *(const uint4*)gAl;
        uint4 vbh = *(const uint4*)gBh;
        uint4 vbl = *(const uint4*)gBl;
        *(uint4*)(sAh + soff) = vah;
        *(uint4*)(sAl + soff) = val;
        *(uint4*)(sBh + soff) = vbh;
        *(uint4*)(sBl + soff) = vbl;
    }
    __syncthreads();

    const int nsteps = K / 16;
    uint4 pah, pal, pbh, pbl;
    for (int ks = 0; ks < nsteps; ks++) {
        const int buf = ks & 1;
        const unsigned bofs = (unsigned)(buf * STG) * 2u;   // bytes

        if (ks + 1 < nsteps) {
            int k = (ks + 1) * 16;
            pah = *(const uint4*)(gAh + k);
            pal = *(const uint4*)(gAl + k);
            pbh = *(const uint4*)(gBh + k);
            pbl = *(const uint4*)(gBl + k);
        }

        // load B fragments
        unsigned bh[8][2], bl[8][2];
        #pragma unroll
        for (int nt = 0; nt < 8; nt++) {
            ldsm_x2(bh[nt], aBh[nt] + bofs);
            ldsm_x2(bl[nt], aBl[nt] + bofs);
        }
        // A fragments + mma
        #pragma unroll
        for (int mt = 0; mt < 2; mt++) {
            unsigned ah[4], al[4];
            ldsm_x4(ah, aAh[mt] + bofs);
            ldsm_x4(al, aAl[mt] + bofs);
            #pragma unroll
            for (int nt = 0; nt < 8; nt++) {
                mma_bf16(acc[mt][nt], ah, bh[nt]);
                mma_bf16(acc[mt][nt], ah, bl[nt]);
                mma_bf16(acc[mt][nt], al, bh[nt]);
            }
        }

        if (ks + 1 < nsteps) {
            const int nb = (ks + 1) & 1;
            __nv_bfloat16* dAh = sAh + nb*STG + soff;
            __nv_bfloat16* dAl = sAl + nb*STG + soff;
            __nv_bfloat16* dBh = sBh + nb*STG + soff;
            __nv_bfloat16* dBl = sBl + nb*STG + soff;
            *(uint4*)dAh = pah;
            *(uint4*)dAl = pal;
            *(uint4*)dBh = pbh;
            *(uint4*)dBl = pbl;
            __syncthreads();
        }
    }

    // epilogue: scale*(acc + bias)
    #pragma unroll
    for (int mt = 0; mt < 2; mt++) {
        int r0 = m0 + wm*32 + mt*16 + (lane >> 2);
        int r1 = r0 + 8;
        #pragma unroll
        for (int nt = 0; nt < 8; nt++) {
            int col = n0 + wn*64 + nt*8 + 2*(lane & 3);
            float2 bv = *(const float2*)&bias[col];
            float2 o0, o1;
            o0.x = scale * (acc[mt][nt][0] + bv.x);
            o0.y = scale * (acc[mt][nt][1] + bv.y);
            o1.x = scale * (acc[mt][nt][2] + bv.x);
            o1.y = scale * (acc[mt][nt][3] + bv.y);
            *(float2*)&C[(size_t)r0 * N + col] = o0;
            *(float2*)&C[(size_t)r1 * N + col] = o1;
        }
    }
}

// ---------------------------------------------------------------------------
// Axial attention core (fp32): one (batch, line, head) per block. 56 pos, D=64.
// ---------------------------------------------------------------------------
struct __align__(16) AttnSmem {
    float Qs[HH * DH];   // [y][d]; reused as P[56*56] after scores
    float Kt[DH * HH];   // [d][y] transposed
    float Vs[HH * DH];   // [y][d]
};

__device__ __forceinline__ void attn_core(
    const float* __restrict__ qg, int qstride,
    const float* __restrict__ kg,
    const float* __restrict__ vg, int vstride,
    float* __restrict__ og, int ostride,
    AttnSmem* sm)
{
    const int tid  = threadIdx.x;
    const int lane = tid & 31;
    const int warp = tid >> 5;

    for (int idx = tid; idx < HH * 16; idx += 256) {
        int y = idx >> 4;
        int j = (idx & 15) * 4;
        float4 q4 = *(const float4*)(qg + (size_t)y * qstride + j);
        *(float4*)&sm->Qs[y * DH + j] = q4;
        float4 k4 = *(const float4*)(kg + (size_t)y * qstride + j);
        sm->Kt[(j+0) * HH + y] = k4.x;
        sm->Kt[(j+1) * HH + y] = k4.y;
        sm->Kt[(j+2) * HH + y] = k4.z;
        sm->Kt[(j+3) * HH + y] = k4.w;
        float4 v4 = *(const float4*)(vg + (size_t)y * vstride + j);
        *(float4*)&sm->Vs[y * DH + j] = v4;
    }
    __syncthreads();

    const int  xbase = warp * 7;
    const int  y1    = lane + 32;
    const bool hasY1 = (y1 < HH);

    float acc0[7], acc1[7];
    #pragma unroll
    for (int xi = 0; xi < 7; xi++) { acc0[xi] = 0.0f; acc1[xi] = 0.0f; }

    #pragma unroll 1
    for (int d0 = 0; d0 < DH; d0 += 16) {
        float kr0[16], kr1[16];
        #pragma unroll
        for (int t = 0; t < 16; t++) {
            kr0[t] = sm->Kt[(d0+t) * HH + lane];
            kr1[t] = hasY1 ? sm->Kt[(d0+t) * HH + y1] : 0.0f;
        }
        #pragma unroll
        for (int xi = 0; xi < 7; xi++) {
            const float4* q4 = (const float4*)&sm->Qs[(xbase+xi) * DH + d0];
            #pragma unroll
            for (int t4 = 0; t4 < 4; t4++) {
                float4 qv = q4[t4];
                acc0[xi] = fmaf(qv.x, kr0[t4*4+0], acc0[xi]);
                acc0[xi] = fmaf(qv.y, kr0[t4*4+1], acc0[xi]);
                acc0[xi] = fmaf(qv.z, kr0[t4*4+2], acc0[xi]);
                acc0[xi] = fmaf(qv.w, kr0[t4*4+3], acc0[xi]);
                acc1[xi] = fmaf(qv.x, kr1[t4*4+0], acc1[xi]);
                acc1[xi] = fmaf(qv.y, kr1[t4*4+1], acc1[xi]);
                acc1[xi] = fmaf(qv.z, kr1[t4*4+2], acc1[xi]);
                acc1[xi] = fmaf(qv.w, kr1[t4*4+3], acc1[xi]);
            }
        }
    }

    #pragma unroll
    for (int xi = 0; xi < 7; xi++) {
        float m = acc0[xi];
        if (hasY1) m = fmaxf(m, acc1[xi]);
        #pragma unroll
        for (int off = 16; off > 0; off >>= 1)
            m = fmaxf(m, __shfl_xor_sync(0xffffffffu, m, off));
        float e0 = expf(acc0[xi] - m);
        float e1 = hasY1 ? expf(acc1[xi] - m) : 0.0f;
        float s = e0 + e1;
        #pragma unroll
        for (int off = 16; off > 0; off >>= 1)
            s += __shfl_xor_sync(0xffffffffu, s, off);
        float inv = 1.0f / s;
        acc0[xi] = e0 * inv;
        acc1[xi] = e1 * inv;
    }

    __syncthreads();
    float* P = sm->Qs;
    #pragma unroll
    for (int xi = 0; xi < 7; xi++) {
        P[(xbase+xi) * HH + lane] = acc0[xi];
        if (hasY1) P[(xbase+xi) * HH + y1] = acc1[xi];
    }
    __syncthreads();

    const int d1 = lane + 32;
    float o0[7], o1[7];
    #pragma unroll
    for (int xi = 0; xi < 7; xi++) { o0[xi] = 0.0f; o1[xi] = 0.0f; }

    #pragma unroll 1
    for (int y0 = 0; y0 < HH; y0 += 8) {
        float vr0[8], vr1[8];
        #pragma unroll
        for (int t = 0; t < 8; t++) {
            vr0[t] = sm->Vs[(y0+t) * DH + lane];
            vr1[t] = sm->Vs[(y0+t) * DH + d1];
        }
        #pragma unroll
        for (int xi = 0; xi < 7; xi++) {
            const float4* p4 = (const float4*)&P[(xbase+xi) * HH + y0];
            float4 pa = p4[0], pb = p4[1];
            o0[xi] = fmaf(pa.x, vr0[0], o0[xi]);
            o0[xi] = fmaf(pa.y, vr0[1], o0[xi]);
            o0[xi] = fmaf(pa.z, vr0[2], o0[xi]);
            o0[xi] = fmaf(pa.w, vr0[3], o0[xi]);
            o0[xi] = fmaf(pb.x, vr0[4], o0[xi]);
            o0[xi] = fmaf(pb.y, vr0[5], o0[xi]);
            o0[xi] = fmaf(pb.z, vr0[6], o0[xi]);
            o0[xi] = fmaf(pb.w, vr0[7], o0[xi]);
            o1[xi] = fmaf(pa.x, vr1[0], o1[xi]);
            o1[xi] = fmaf(pa.y, vr1[1], o1[xi]);
            o1[xi] = fmaf(pa.z, vr1[2], o1[xi]);
            o1[xi] = fmaf(pa.w, vr1[3], o1[xi]);
            o1[xi] = fmaf(pb.x, vr1[4], o1[xi]);
            o1[xi] = fmaf(pb.y, vr1[5], o1[xi]);
            o1[xi] = fmaf(pb.z, vr1[6], o1[xi]);
            o1[xi] = fmaf(pb.w, vr1[7], o1[xi]);
        }
    }

    #pragma unroll
    for (int xi = 0; xi < 7; xi++) {
        float* orow = og + (size_t)(xbase+xi) * ostride;
        orow[lane] = o0[xi];
        orow[d1]   = o1[xi];
    }
}

__global__ __launch_bounds__(256)
void attn_w_kernel(const float* __restrict__ q, const float* __restrict__ k,
                   const float* __restrict__ v, float* __restrict__ vw)
{
    __shared__ AttnSmem sm;
    const int n = blockIdx.x, h = blockIdx.y, b = blockIdx.z;
    size_t qoff = ((size_t)(b*HH + h) * WW) * EMB + n * DH;
    float* og = vw + ((size_t)((b*HH + h) * NH + n) * WW) * DH;
    attn_core(q + qoff, EMB, k + qoff, v + qoff, EMB, og, DH, &sm);
}

__global__ __launch_bounds__(256)
void attn_h_kernel(const float* __restrict__ q, const float* __restrict__ k,
                   const float* __restrict__ vw, float* __restrict__ out)
{
    __shared__ AttnSmem sm;
    const int n = blockIdx.x, w = blockIdx.y, b = blockIdx.z;
    size_t qoff = ((size_t)b * HH * WW + w) * EMB + n * DH;
    const float* vg = vw + ((size_t)(b*HH*NH + n) * WW + w) * DH;
    attn_core(q + qoff, WW*EMB, k + qoff, vg, NH*WW*DH, out + qoff, WW*EMB, &sm);
}

// ---------------------------------------------------------------------------
extern "C" void kernel_launch(void* const* d_in, const int* in_sizes, int n_in,
                              void* d_out, int out_size)
{
    const float* x  = (const float*)d_in[0];
    const float* Wq = (const float*)d_in[1];
    const float* bq = (const float*)d_in[2];
    const float* Wk = (const float*)d_in[3];
    const float* bk = (const float*)d_in[4];
    const float* Wv = (const float*)d_in[5];
    const float* bv = (const float*)d_in[6];
    const float* Wo = (const float*)d_in[7];
    const float* bo = (const float*)d_in[8];

    float *q, *k, *v, *vw, *ao;
    __nv_bfloat16 *xh, *xl, *aoh, *aol, *wh, *wl;
    cudaGetSymbolAddress((void**)&q,   g_q);
    cudaGetSymbolAddress((void**)&k,   g_k);
    cudaGetSymbolAddress((void**)&v,   g_v);
    cudaGetSymbolAddress((void**)&vw,  g_vw);
    cudaGetSymbolAddress((void**)&ao,  g_ao);
    cudaGetSymbolAddress((void**)&xh,  g_xh);
    cudaGetSymbolAddress((void**)&xl,  g_xl);
    cudaGetSymbolAddress((void**)&aoh, g_aoh);
    cudaGetSymbolAddress((void**)&aol, g_aol);
    cudaGetSymbolAddress((void**)&wh,  g_wh);
    cudaGetSymbolAddress((void**)&wl,  g_wl);

    static bool attr_set = false;
    if (!attr_set) {
        cudaFuncSetAttribute(gemm_mma_split,
                             cudaFuncAttributeMaxDynamicSharedMemorySize, 8*STG*2);
        attr_set = true;
    }

    const int WSZ = EMB * EMB;                        // 589824
    const int XSZ = TOK * EMB;                        // 38535168

    split_f32_bf16<<<XSZ/1024, 256>>>(x,  xh, xl, XSZ);
    split_f32_bf16<<<WSZ/1024, 256>>>(Wq, wh + 0*(size_t)WSZ, wl + 0*(size_t)WSZ, WSZ);
    split_f32_bf16<<<WSZ/1024, 256>>>(Wk, wh + 1*(size_t)WSZ, wl + 1*(size_t)WSZ, WSZ);
    split_f32_bf16<<<WSZ/1024, 256>>>(Wv, wh + 2*(size_t)WSZ, wl + 2*(size_t)WSZ, WSZ);
    split_f32_bf16<<<WSZ/1024, 256>>>(Wo, wh + 3*(size_t)WSZ, wl + 3*(size_t)WSZ, WSZ);

    dim3 gg(EMB/128, TOK/128);   // (6, 392)
    size_t shm = 8*STG*2;        // 49152 B
    gemm_mma_split<<<gg, 256, shm>>>(xh, xl, wh + 0*(size_t)WSZ, wl + 0*(size_t)WSZ,
                                     bq, q, TOK, EMB, EMB, 1.0f);
    gemm_mma_split<<<gg, 256, shm>>>(xh, xl, wh + 1*(size_t)WSZ, wl + 1*(size_t)WSZ,
                                     bk, k, TOK, EMB, EMB, SCALING);
    gemm_mma_split<<<gg, 256, shm>>>(xh, xl, wh + 2*(size_t)WSZ, wl + 2*(size_t)WSZ,
                                     bv, v, TOK, EMB, EMB, 1.0f);

    dim3 ga(NH, HH, BB);         // (12, 56, 16)
    attn_w_kernel<<<ga, 256>>>(q, k, v, vw);
    attn_h_kernel<<<ga, 256>>>(q, k, vw, ao);

    split_f32_bf16<<<XSZ/1024, 256>>>(ao, aoh, aol, XSZ);
    gemm_mma_split<<<gg, 256, shm>>>(aoh, aol, wh + 3*(size_t)WSZ, wl + 3*(size_t)WSZ,
                                     bo, (float*)d_out, TOK, EMB, EMB, 1.0f);
}

// round 4
// speedup vs baseline: 1.1431x; 1.1431x over previous
#include <cuda_runtime.h>
#include <cuda_bf16.h>
#include <math.h>

#define BB 16
#define HH 56
#define WW 56
#define EMB 768
#define NH 12
#define DH 64
#define TOK (BB*HH*WW)          // 50176
#define SCALING 0.125f          // 64^-0.5

// ---- GEMM tiling (mma.sync path; tcgen05 unavailable: harness targets compute_100) ----
#define TM 128
#define TN 192
#define BK 32
#define NKBLK (EMB/BK)          // 24
#define NTHREADS 384            // 12 warps: 4 (M) x 3 (N)
#define A_STG_BYTES (TM*128)    // 16384
#define B_STG_BYTES (TN*128)    // 24576
#define STG_BYTES (A_STG_BYTES + B_STG_BYTES)   // 40960
#define NSTAGE 3
#define GEMM_SMEM (NSTAGE*STG_BYTES)            // 122880

// ---------------- scratch (static device arrays; no allocation) ----------------
__device__ float g_q [(size_t)TOK * EMB];
__device__ float g_k [(size_t)TOK * EMB];
__device__ float g_v [(size_t)TOK * EMB];
__device__ float g_vw[(size_t)TOK * EMB];
__device__ float g_ao[(size_t)TOK * EMB];

__device__ __nv_bfloat16 g_xh [(size_t)TOK * EMB];
__device__ __nv_bfloat16 g_xl [(size_t)TOK * EMB];
__device__ __nv_bfloat16 g_aoh[(size_t)TOK * EMB];
__device__ __nv_bfloat16 g_aol[(size_t)TOK * EMB];
__device__ __nv_bfloat16 g_wh [(size_t)4 * EMB * EMB];
__device__ __nv_bfloat16 g_wl [(size_t)4 * EMB * EMB];

// ---------------------------------------------------------------------------
// Split fp32 -> (hi, lo) bf16 pair:  x ~= hi + lo, residual ~ 2^-17 * |x|
// ---------------------------------------------------------------------------
__global__ void split_f32_bf16(const float* __restrict__ s,
                               __nv_bfloat16* __restrict__ hi,
                               __nv_bfloat16* __restrict__ lo, int n)
{
    int i = (blockIdx.x * blockDim.x + threadIdx.x) * 4;
    if (i >= n) return;
    float4 v = *(const float4*)(s + i);
    __nv_bfloat16 h0 = __float2bfloat16_rn(v.x);
    __nv_bfloat16 h1 = __float2bfloat16_rn(v.y);
    __nv_bfloat16 h2 = __float2bfloat16_rn(v.z);
    __nv_bfloat16 h3 = __float2bfloat16_rn(v.w);
    __nv_bfloat16 l0 = __float2bfloat16_rn(v.x - __bfloat162float(h0));
    __nv_bfloat16 l1 = __float2bfloat16_rn(v.y - __bfloat162float(h1));
    __nv_bfloat16 l2 = __float2bfloat16_rn(v.z - __bfloat162float(h2));
    __nv_bfloat16 l3 = __float2bfloat16_rn(v.w - __bfloat162float(h3));
    *(__nv_bfloat162*)(hi + i)     = __nv_bfloat162(h0, h1);
    *(__nv_bfloat162*)(hi + i + 2) = __nv_bfloat162(h2, h3);
    *(__nv_bfloat162*)(lo + i)     = __nv_bfloat162(l0, l1);
    *(__nv_bfloat162*)(lo + i + 2) = __nv_bfloat162(l2, l3);
}

// ---------------------------------------------------------------------------
// helpers (all compute_100-safe)
// ---------------------------------------------------------------------------
__device__ __forceinline__ unsigned smem_u32(const void* p) {
    return (unsigned)__cvta_generic_to_shared(p);
}
__device__ __forceinline__ void cp16(unsigned dst, const void* src) {
    asm volatile("cp.async.cg.shared.global [%0], [%1], 16;" :: "r"(dst), "l"(src));
}
__device__ __forceinline__ void ldsm_x4(unsigned* r, unsigned addr) {
    asm volatile("ldmatrix.sync.aligned.m8n8.x4.shared.b16 {%0,%1,%2,%3}, [%4];"
                 : "=r"(r[0]), "=r"(r[1]), "=r"(r[2]), "=r"(r[3]) : "r"(addr));
}
__device__ __forceinline__ void mma_bf16(float* c, const unsigned* a, unsigned b0, unsigned b1) {
    asm volatile("mma.sync.aligned.m16n8k16.row.col.f32.bf16.bf16.f32 "
                 "{%0,%1,%2,%3}, {%4,%5,%6,%7}, {%8,%9}, {%0,%1,%2,%3};"
                 : "+f"(c[0]), "+f"(c[1]), "+f"(c[2]), "+f"(c[3])
                 : "r"(a[0]), "r"(a[1]), "r"(a[2]), "r"(a[3]), "r"(b0), "r"(b1));
}

// ---------------------------------------------------------------------------
// Pipelined split-bf16 GEMM on mma.sync:
//   C[m,n] = scale*( sum_k A[m,k]*B[n,k] + bias[n] ),  A~Ah+Al, B~Bh+Bl,
//   acc += ah*bh + al*bh + ah*bl  (fp32 accum; al*bl dropped ~2^-34).
// Tile 128x192, BK=32, 3-stage cp.async, 384 threads (warps 4x3).
// Smem row layout (128B per m/n row per K-block):
//   [s0 hi k0-15 | s0 lo k0-15 | s1 hi k16-31 | s1 lo k16-31], SW128 XOR swizzle.
// ---------------------------------------------------------------------------
__global__ __launch_bounds__(NTHREADS, 1)
void gemm_mma_split(const __nv_bfloat16* __restrict__ Ah, const __nv_bfloat16* __restrict__ Al,
                    const __nv_bfloat16* __restrict__ Bh, const __nv_bfloat16* __restrict__ Bl,
                    const float* __restrict__ bias, float* __restrict__ C, float scale)
{
    extern __shared__ __align__(1024) char smraw[];
    const unsigned sbase = smem_u32(smraw);

    const int tid  = threadIdx.x;
    const int lane = tid & 31;
    const int warp = tid >> 5;
    const int wm   = warp & 3;           // 0..3  (M 32-chunks)
    const int wn   = warp >> 2;          // 0..2  (N 64-chunks)
    const int m0   = blockIdx.y * TM;
    const int n0   = blockIdx.x * TN;

    // ---- stage loader: 16B per cp.async, hi/lo interleaved, SW128 swizzle ----
    auto load_stage = [&](int kb, int buf) {
        const unsigned so = sbase + buf * STG_BYTES;
        const int kofs = kb * BK;
        // A: 128 rows x 8 chunks
        for (int i = tid; i < TM * 8; i += NTHREADS) {
            int row = i >> 3, ch = i & 7;
            int s = ch >> 2, p = (ch >> 1) & 1, c = ch & 1;
            const __nv_bfloat16* src =
                (p ? Al : Ah) + (size_t)(m0 + row) * EMB + kofs + s * 16 + c * 8;
            unsigned dst = so + row * 128 + ((ch * 16) ^ ((row & 7) << 4));
            cp16(dst, src);
        }
        // B: 192 rows x 8 chunks
        for (int i = tid; i < TN * 8; i += NTHREADS) {
            int row = i >> 3, ch = i & 7;
            int s = ch >> 2, p = (ch >> 1) & 1, c = ch & 1;
            const __nv_bfloat16* src =
                (p ? Bl : Bh) + (size_t)(n0 + row) * EMB + kofs + s * 16 + c * 8;
            unsigned dst = so + A_STG_BYTES + row * 128 + ((ch * 16) ^ ((row & 7) << 4));
            cp16(dst, src);
        }
        asm volatile("cp.async.commit_group;" ::: "memory");
    };

    float acc[2][8][4];
    #pragma unroll
    for (int mt = 0; mt < 2; mt++)
        #pragma unroll
        for (int nt = 0; nt < 8; nt++)
            #pragma unroll
            for (int r = 0; r < 4; r++) acc[mt][nt][r] = 0.0f;

    // per-lane ldmatrix relative offsets (within a stage buffer)
    const int laneR = lane & 15;
    const int laneC = (lane >> 4) * 16;       // 0 or 16
    unsigned relA[2], relB[4];
    #pragma unroll
    for (int mt = 0; mt < 2; mt++) {
        int row = wm * 32 + mt * 16 + laneR;
        relA[mt] = row * 128 + ((row & 7) << 4);   // store row term + xor key merged later
    }
    #pragma unroll
    for (int nt2 = 0; nt2 < 4; nt2++) {
        int row = wn * 64 + nt2 * 16 + laneR;
        relB[nt2] = A_STG_BYTES + row * 128 + ((row & 7) << 4);
    }
    // NOTE: relX holds row*128 + xorkey<<0 where xorkey=(row&7)<<4; actual addr =
    //   base + row*128 + ((s*64+p*32+laneC) ^ xorkey). We recompute cleanly below.
    unsigned xorA[2], rowA[2], xorB[4], rowB[4];
    #pragma unroll
    for (int mt = 0; mt < 2; mt++) {
        int row = wm * 32 + mt * 16 + laneR;
        rowA[mt] = row * 128; xorA[mt] = (row & 7) << 4;
    }
    #pragma unroll
    for (int nt2 = 0; nt2 < 4; nt2++) {
        int row = wn * 64 + nt2 * 16 + laneR;
        rowB[nt2] = A_STG_BYTES + row * 128; xorB[nt2] = (row & 7) << 4;
    }

    // prologue: stages 0,1
    load_stage(0, 0);
    load_stage(1, 1);

    for (int kb = 0; kb < NKBLK; kb++) {
        const int buf = kb % NSTAGE;
        if (kb < NKBLK - 1) asm volatile("cp.async.wait_group 1;" ::: "memory");
        else                asm volatile("cp.async.wait_group 0;" ::: "memory");
        __syncthreads();

        const unsigned so = sbase + buf * STG_BYTES;

        #pragma unroll
        for (int s = 0; s < 2; s++) {
            const unsigned hiOfs = s * 64 + laneC;       // p=0
            const unsigned loOfs = s * 64 + 32 + laneC;  // p=1

            unsigned ah[2][4], bh[4][4];
            #pragma unroll
            for (int mt = 0; mt < 2; mt++)
                ldsm_x4(ah[mt], so + rowA[mt] + (hiOfs ^ xorA[mt]));
            #pragma unroll
            for (int nt2 = 0; nt2 < 4; nt2++)
                ldsm_x4(bh[nt2], so + rowB[nt2] + (hiOfs ^ xorB[nt2]));

            // term hh
            #pragma unroll
            for (int mt = 0; mt < 2; mt++)
                #pragma unroll
                for (int nt = 0; nt < 8; nt++)
                    mma_bf16(acc[mt][nt], ah[mt], bh[nt >> 1][nt & 1], bh[nt >> 1][(nt & 1) + 2]);

            // term lh (al * bh)
            unsigned al[2][4];
            #pragma unroll
            for (int mt = 0; mt < 2; mt++)
                ldsm_x4(al[mt], so + rowA[mt] + (loOfs ^ xorA[mt]));
            #pragma unroll
            for (int mt = 0; mt < 2; mt++)
                #pragma unroll
                for (int nt = 0; nt < 8; nt++)
                    mma_bf16(acc[mt][nt], al[mt], bh[nt >> 1][nt & 1], bh[nt >> 1][(nt & 1) + 2]);

            // term hl (ah * bl)
            unsigned bl[4][4];
            #pragma unroll
            for (int nt2 = 0; nt2 < 4; nt2++)
                ldsm_x4(bl[nt2], so + rowB[nt2] + (loOfs ^ xorB[nt2]));
            #pragma unroll
            for (int mt = 0; mt < 2; mt++)
                #pragma unroll
                for (int nt = 0; nt < 8; nt++)
                    mma_bf16(acc[mt][nt], ah[mt], bl[nt >> 1][nt & 1], bl[nt >> 1][(nt & 1) + 2]);
        }

        if (kb + 2 < NKBLK) load_stage(kb + 2, (kb + 2) % NSTAGE);
    }

    // ---- epilogue: direct register -> C with bias + scale ----
    #pragma unroll
    for (int mt = 0; mt < 2; mt++) {
        int r0 = m0 + wm * 32 + mt * 16 + (lane >> 2);
        int r1 = r0 + 8;
        #pragma unroll
        for (int nt = 0; nt < 8; nt++) {
            int col = n0 + wn * 64 + nt * 8 + 2 * (lane & 3);
            float2 bv = *(const float2*)&bias[col];
            float2 o0, o1;
            o0.x = scale * (acc[mt][nt][0] + bv.x);
            o0.y = scale * (acc[mt][nt][1] + bv.y);
            o1.x = scale * (acc[mt][nt][2] + bv.x);
            o1.y = scale * (acc[mt][nt][3] + bv.y);
            *(float2*)&C[(size_t)r0 * EMB + col] = o0;
            *(float2*)&C[(size_t)r1 * EMB + col] = o1;
        }
    }
}

// ---------------------------------------------------------------------------
// Axial attention core (fp32): one (batch, line, head) per block. 56 pos, D=64.
// ---------------------------------------------------------------------------
struct __align__(16) AttnSmem {
    float Qs[HH * DH];   // [y][d]; reused as P[56*56] after scores
    float Kt[DH * HH];   // [d][y] transposed
    float Vs[HH * DH];   // [y][d]
};

__device__ __forceinline__ void attn_core(
    const float* __restrict__ qg, int qstride,
    const float* __restrict__ kg,
    const float* __restrict__ vg, int vstride,
    float* __restrict__ og, int ostride,
    AttnSmem* sm)
{
    const int tid  = threadIdx.x;
    const int lane = tid & 31;
    const int warp = tid >> 5;

    for (int idx = tid; idx < HH * 16; idx += 256) {
        int y = idx >> 4;
        int j = (idx & 15) * 4;
        float4 q4 = *(const float4*)(qg + (size_t)y * qstride + j);
        *(float4*)&sm->Qs[y * DH + j] = q4;
        float4 k4 = *(const float4*)(kg + (size_t)y * qstride + j);
        sm->Kt[(j+0) * HH + y] = k4.x;
        sm->Kt[(j+1) * HH + y] = k4.y;
        sm->Kt[(j+2) * HH + y] = k4.z;
        sm->Kt[(j+3) * HH + y] = k4.w;
        float4 v4 = *(const float4*)(vg + (size_t)y * vstride + j);
        *(float4*)&sm->Vs[y * DH + j] = v4;
    }
    __syncthreads();

    const int  xbase = warp * 7;
    const int  y1    = lane + 32;
    const bool hasY1 = (y1 < HH);

    float acc0[7], acc1[7];
    #pragma unroll
    for (int xi = 0; xi < 7; xi++) { acc0[xi] = 0.0f; acc1[xi] = 0.0f; }

    #pragma unroll 1
    for (int d0 = 0; d0 < DH; d0 += 16) {
        float kr0[16], kr1[16];
        #pragma unroll
        for (int t = 0; t < 16; t++) {
            kr0[t] = sm->Kt[(d0+t) * HH + lane];
            kr1[t] = hasY1 ? sm->Kt[(d0+t) * HH + y1] : 0.0f;
        }
        #pragma unroll
        for (int xi = 0; xi < 7; xi++) {
            const float4* q4 = (const float4*)&sm->Qs[(xbase+xi) * DH + d0];
            #pragma unroll
            for (int t4 = 0; t4 < 4; t4++) {
                float4 qv = q4[t4];
                acc0[xi] = fmaf(qv.x, kr0[t4*4+0], acc0[xi]);
                acc0[xi] = fmaf(qv.y, kr0[t4*4+1], acc0[xi]);
                acc0[xi] = fmaf(qv.z, kr0[t4*4+2], acc0[xi]);
                acc0[xi] = fmaf(qv.w, kr0[t4*4+3], acc0[xi]);
                acc1[xi] = fmaf(qv.x, kr1[t4*4+0], acc1[xi]);
                acc1[xi] = fmaf(qv.y, kr1[t4*4+1], acc1[xi]);
                acc1[xi] = fmaf(qv.z, kr1[t4*4+2], acc1[xi]);
                acc1[xi] = fmaf(qv.w, kr1[t4*4+3], acc1[xi]);
            }
        }
    }

    #pragma unroll
    for (int xi = 0; xi < 7; xi++) {
        float m = acc0[xi];
        if (hasY1) m = fmaxf(m, acc1[xi]);
        #pragma unroll
        for (int off = 16; off > 0; off >>= 1)
            m = fmaxf(m, __shfl_xor_sync(0xffffffffu, m, off));
        float e0 = expf(acc0[xi] - m);
        float e1 = hasY1 ? expf(acc1[xi] - m) : 0.0f;
        float s = e0 + e1;
        #pragma unroll
        for (int off = 16; off > 0; off >>= 1)
            s += __shfl_xor_sync(0xffffffffu, s, off);
        float inv = 1.0f / s;
        acc0[xi] = e0 * inv;
        acc1[xi] = e1 * inv;
    }

    __syncthreads();
    float* P = sm->Qs;
    #pragma unroll
    for (int xi = 0; xi < 7; xi++) {
        P[(xbase+xi) * HH + lane] = acc0[xi];
        if (hasY1) P[(xbase+xi) * HH + y1] = acc1[xi];
    }
    __syncthreads();

    const int d1 = lane + 32;
    float o0[7], o1[7];
    #pragma unroll
    for (int xi = 0; xi < 7; xi++) { o0[xi] = 0.0f; o1[xi] = 0.0f; }

    #pragma unroll 1
    for (int y0 = 0; y0 < HH; y0 += 8) {
        float vr0[8], vr1[8];
        #pragma unroll
        for (int t = 0; t < 8; t++) {
            vr0[t] = sm->Vs[(y0+t) * DH + lane];
            vr1[t] = sm->Vs[(y0+t) * DH + d1];
        }
        #pragma unroll
        for (int xi = 0; xi < 7; xi++) {
            const float4* p4 = (const float4*)&P[(xbase+xi) * HH + y0];
            float4 pa = p4[0], pb = p4[1];
            o0[xi] = fmaf(pa.x, vr0[0], o0[xi]);
            o0[xi] = fmaf(pa.y, vr0[1], o0[xi]);
            o0[xi] = fmaf(pa.z, vr0[2], o0[xi]);
            o0[xi] = fmaf(pa.w, vr0[3], o0[xi]);
            o0[xi] = fmaf(pb.x, vr0[4], o0[xi]);
            o0[xi] = fmaf(pb.y, vr0[5], o0[xi]);
            o0[xi] = fmaf(pb.z, vr0[6], o0[xi]);
            o0[xi] = fmaf(pb.w, vr0[7], o0[xi]);
            o1[xi] = fmaf(pa.x, vr1[0], o1[xi]);
            o1[xi] = fmaf(pa.y, vr1[1], o1[xi]);
            o1[xi] = fmaf(pa.z, vr1[2], o1[xi]);
            o1[xi] = fmaf(pa.w, vr1[3], o1[xi]);
            o1[xi] = fmaf(pb.x, vr1[4], o1[xi]);
            o1[xi] = fmaf(pb.y, vr1[5], o1[xi]);
            o1[xi] = fmaf(pb.z, vr1[6], o1[xi]);
            o1[xi] = fmaf(pb.w, vr1[7], o1[xi]);
        }
    }

    #pragma unroll
    for (int xi = 0; xi < 7; xi++) {
        float* orow = og + (size_t)(xbase+xi) * ostride;
        orow[lane] = o0[xi];
        orow[d1]   = o1[xi];
    }
}

__global__ __launch_bounds__(256)
void attn_w_kernel(const float* __restrict__ q, const float* __restrict__ k,
                   const float* __restrict__ v, float* __restrict__ vw)
{
    __shared__ AttnSmem sm;
    const int n = blockIdx.x, h = blockIdx.y, b = blockIdx.z;
    size_t qoff = ((size_t)(b*HH + h) * WW) * EMB + n * DH;
    float* og = vw + ((size_t)((b*HH + h) * NH + n) * WW) * DH;
    attn_core(q + qoff, EMB, k + qoff, v + qoff, EMB, og, DH, &sm);
}

__global__ __launch_bounds__(256)
void attn_h_kernel(const float* __restrict__ q, const float* __restrict__ k,
                   const float* __restrict__ vw, float* __restrict__ out)
{
    __shared__ AttnSmem sm;
    const int n = blockIdx.x, w = blockIdx.y, b = blockIdx.z;
    size_t qoff = ((size_t)b * HH * WW + w) * EMB + n * DH;
    const float* vg = vw + ((size_t)(b*HH*NH + n) * WW + w) * DH;
    attn_core(q + qoff, WW*EMB, k + qoff, vg, NH*WW*DH, out + qoff, WW*EMB, &sm);
}

// ---------------------------------------------------------------------------
extern "C" void kernel_launch(void* const* d_in, const int* in_sizes, int n_in,
                              void* d_out, int out_size)
{
    const float* x  = (const float*)d_in[0];
    const float* Wq = (const float*)d_in[1];
    const float* bq = (const float*)d_in[2];
    const float* Wk = (const float*)d_in[3];
    const float* bk = (const float*)d_in[4];
    const float* Wv = (const float*)d_in[5];
    const float* bv = (const float*)d_in[6];
    const float* Wo = (const float*)d_in[7];
    const float* bo = (const float*)d_in[8];

    float *q, *k, *v, *vw, *ao;
    __nv_bfloat16 *xh, *xl, *aoh, *aol, *wh, *wl;
    cudaGetSymbolAddress((void**)&q,   g_q);
    cudaGetSymbolAddress((void**)&k,   g_k);
    cudaGetSymbolAddress((void**)&v,   g_v);
    cudaGetSymbolAddress((void**)&vw,  g_vw);
    cudaGetSymbolAddress((void**)&ao,  g_ao);
    cudaGetSymbolAddress((void**)&xh,  g_xh);
    cudaGetSymbolAddress((void**)&xl,  g_xl);
    cudaGetSymbolAddress((void**)&aoh, g_aoh);
    cudaGetSymbolAddress((void**)&aol, g_aol);
    cudaGetSymbolAddress((void**)&wh,  g_wh);
    cudaGetSymbolAddress((void**)&wl,  g_wl);

    static bool attr_set = false;
    if (!attr_set) {
        cudaFuncSetAttribute(gemm_mma_split,
                             cudaFuncAttributeMaxDynamicSharedMemorySize, GEMM_SMEM);
        attr_set = true;
    }

    const int WSZ = EMB * EMB;
    const int XSZ = TOK * EMB;

    split_f32_bf16<<<XSZ/1024, 256>>>(x,  xh, xl, XSZ);
    split_f32_bf16<<<WSZ/1024, 256>>>(Wq, wh + 0*(size_t)WSZ, wl + 0*(size_t)WSZ, WSZ);
    split_f32_bf16<<<WSZ/1024, 256>>>(Wk, wh + 1*(size_t)WSZ, wl + 1*(size_t)WSZ, WSZ);
    split_f32_bf16<<<WSZ/1024, 256>>>(Wv, wh + 2*(size_t)WSZ, wl + 2*(size_t)WSZ, WSZ);
    split_f32_bf16<<<WSZ/1024, 256>>>(Wo, wh + 3*(size_t)WSZ, wl + 3*(size_t)WSZ, WSZ);

    dim3 gg(EMB/TN, TOK/TM);     // (4, 392) — N-tiles fastest for L2 A reuse
    gemm_mma_split<<<gg, NTHREADS, GEMM_SMEM>>>(xh, xl, wh + 0*(size_t)WSZ, wl + 0*(size_t)WSZ,
                                                bq, q, 1.0f);
    gemm_mma_split<<<gg, NTHREADS, GEMM_SMEM>>>(xh, xl, wh + 1*(size_t)WSZ, wl + 1*(size_t)WSZ,
                                                bk, k, SCALING);
    gemm_mma_split<<<gg, NTHREADS, GEMM_SMEM>>>(xh, xl, wh + 2*(size_t)WSZ, wl + 2*(size_t)WSZ,
                                                bv, v, 1.0f);

    dim3 ga(NH, HH, BB);         // (12, 56, 16)
    attn_w_kernel<<<ga, 256>>>(q, k, v, vw);
    attn_h_kernel<<<ga, 256>>>(q, k, vw, ao);

    split_f32_bf16<<<XSZ/1024, 256>>>(ao, aoh, aol, XSZ);
    gemm_mma_split<<<gg, NTHREADS, GEMM_SMEM>>>(aoh, aol, wh + 3*(size_t)WSZ, wl + 3*(size_t)WSZ,
                                                bo, (float*)d_out, 1.0f);
}

// round 5
// speedup vs baseline: 1.5627x; 1.3670x over previous
#include <cuda_runtime.h>
#include <cuda_fp16.h>
#include <math.h>

#define BB 16
#define HH 56
#define WW 56
#define EMB 768
#define NH 12
#define DH 64
#define TOK (BB*HH*WW)          // 50176
#define SCALING 0.125f          // 64^-0.5
#define LO_SCALE 2048.0f
#define INV_LO   (1.0f/2048.0f)

// ---- GEMM tiling (mma.sync fp16 2-term; tcgen05 unavailable on compute_100) ----
#define TM 128
#define TN 128
#define BK 64
#define NKBLK (EMB/BK)          // 12
#define NTHREADS 256            // 8 warps: 4 (M) x 2 (N)
#define STG_BYTES 49152         // Ah 16K + Al 16K + Bh 16K
#define NSTAGE 3
#define GEMM_SMEM (NSTAGE*STG_BYTES)   // 147456

// ---------------- scratch (static device arrays; no allocation) ----------------
__device__ float g_q [(size_t)TOK * EMB];
__device__ float g_k [(size_t)TOK * EMB];
__device__ float g_v [(size_t)TOK * EMB];
__device__ float g_vw[(size_t)TOK * EMB];
__device__ float g_ao[(size_t)TOK * EMB];

__device__ __half g_xh  [(size_t)TOK * EMB];
__device__ __half g_xls [(size_t)TOK * EMB];
__device__ __half g_aoh [(size_t)TOK * EMB];
__device__ __half g_aols[(size_t)TOK * EMB];
__device__ __half g_wh  [(size_t)4 * EMB * EMB];   // Wq,Wk,Wv,Wo hi (fp16)

// ---------------------------------------------------------------------------
// Split fp32 -> fp16 hi + scaled fp16 lo:  x ~= h + l*(1/2048)
// ---------------------------------------------------------------------------
__global__ void split_f32_f16s(const float* __restrict__ s,
                               __half* __restrict__ hi,
                               __half* __restrict__ los, int n)
{
    int i = (blockIdx.x * blockDim.x + threadIdx.x) * 4;
    if (i >= n) return;
    float4 v = *(const float4*)(s + i);
    __half h0 = __float2half_rn(v.x);
    __half h1 = __float2half_rn(v.y);
    __half h2 = __float2half_rn(v.z);
    __half h3 = __float2half_rn(v.w);
    __half l0 = __float2half_rn((v.x - __half2float(h0)) * LO_SCALE);
    __half l1 = __float2half_rn((v.y - __half2float(h1)) * LO_SCALE);
    __half l2 = __float2half_rn((v.z - __half2float(h2)) * LO_SCALE);
    __half l3 = __float2half_rn((v.w - __half2float(h3)) * LO_SCALE);
    *(__half2*)(hi + i)      = __halves2half2(h0, h1);
    *(__half2*)(hi + i + 2)  = __halves2half2(h2, h3);
    *(__half2*)(los + i)     = __halves2half2(l0, l1);
    *(__half2*)(los + i + 2) = __halves2half2(l2, l3);
}

// Convert 4 weight matrices fp32 -> fp16 hi (one launch, blockIdx.z selects)
__global__ void conv4_f16(const float* __restrict__ w0, const float* __restrict__ w1,
                          const float* __restrict__ w2, const float* __restrict__ w3,
                          __half* __restrict__ dst, int n)
{
    const float* src = (blockIdx.z == 0) ? w0 : (blockIdx.z == 1) ? w1
                     : (blockIdx.z == 2) ? w2 : w3;
    __half* d = dst + (size_t)blockIdx.z * n;
    int i = (blockIdx.x * blockDim.x + threadIdx.x) * 4;
    if (i >= n) return;
    float4 v = *(const float4*)(src + i);
    *(__half2*)(d + i)     = __halves2half2(__float2half_rn(v.x), __float2half_rn(v.y));
    *(__half2*)(d + i + 2) = __halves2half2(__float2half_rn(v.z), __float2half_rn(v.w));
}

// ---------------------------------------------------------------------------
// helpers (compute_100-safe)
// ---------------------------------------------------------------------------
__device__ __forceinline__ unsigned smem_u32(const void* p) {
    return (unsigned)__cvta_generic_to_shared(p);
}
__device__ __forceinline__ void cp16(unsigned dst, const void* src) {
    asm volatile("cp.async.cg.shared.global [%0], [%1], 16;" :: "r"(dst), "l"(src));
}
__device__ __forceinline__ void ldsm_x4(unsigned* r, unsigned addr) {
    asm volatile("ldmatrix.sync.aligned.m8n8.x4.shared.b16 {%0,%1,%2,%3}, [%4];"
                 : "=r"(r[0]), "=r"(r[1]), "=r"(r[2]), "=r"(r[3]) : "r"(addr));
}
__device__ __forceinline__ void mma_f16(float* c, const unsigned* a, unsigned b0, unsigned b1) {
    asm volatile("mma.sync.aligned.m16n8k16.row.col.f32.f16.f16.f32 "
                 "{%0,%1,%2,%3}, {%4,%5,%6,%7}, {%8,%9}, {%0,%1,%2,%3};"
                 : "+f"(c[0]), "+f"(c[1]), "+f"(c[2]), "+f"(c[3])
                 : "r"(a[0]), "r"(a[1]), "r"(a[2]), "r"(a[3]), "r"(b0), "r"(b1));
}

// ---------------------------------------------------------------------------
// fp16 2-term GEMM:  C[m,n] = scale*( sum_k A[m,k]*B[n,k] + bias[n] )
//   A ~ Ah + Als*(1/2048) (fp16 pair), B ~ Bh (fp16).
//   acc_h += ah*bh ; acc_l += als*bh ; C = scale*(acc_h + acc_l/2048 + bias).
// Tile 128x128, BK=64, 3-stage cp.async, 256 threads (warps 4x2).
// Stage layout: [Ah 128x128B | Als 128x128B | Bh 128x128B], SW128 XOR swizzle.
// ---------------------------------------------------------------------------
__global__ __launch_bounds__(NTHREADS, 1)
void gemm_f16_2t(const __half* __restrict__ Ah, const __half* __restrict__ Als,
                 const __half* __restrict__ Bh,
                 const float* __restrict__ bias, float* __restrict__ C, float scale)
{
    extern __shared__ __align__(1024) char smraw[];
    const unsigned sbase = smem_u32(smraw);

    const int tid  = threadIdx.x;
    const int lane = tid & 31;
    const int warp = tid >> 5;
    const int wm   = warp & 3;           // 0..3  (M 32-chunks)
    const int wn   = warp >> 2;          // 0..1  (N 64-chunks)
    const int m0   = blockIdx.y * TM;
    const int n0   = blockIdx.x * TN;

    auto load_stage = [&](int kb, int buf) {
        const unsigned so = sbase + buf * STG_BYTES;
        const int kofs = kb * BK;
        for (int i = tid; i < TM * 8; i += NTHREADS) {
            int row = i >> 3, ch = i & 7;
            unsigned sw = (unsigned)((ch * 16) ^ ((row & 7) << 4));
            const size_t g = (size_t)(m0 + row) * EMB + kofs + ch * 8;
            cp16(so + row * 128 + sw, Ah + g);
            cp16(so + 16384 + row * 128 + sw, Als + g);
        }
        for (int i = tid; i < TN * 8; i += NTHREADS) {
            int row = i >> 3, ch = i & 7;
            unsigned sw = (unsigned)((ch * 16) ^ ((row & 7) << 4));
            cp16(so + 32768 + row * 128 + sw,
                 Bh + (size_t)(n0 + row) * EMB + kofs + ch * 8);
        }
        asm volatile("cp.async.commit_group;" ::: "memory");
    };

    float acch[2][8][4], accl[2][8][4];
    #pragma unroll
    for (int mt = 0; mt < 2; mt++)
        #pragma unroll
        for (int nt = 0; nt < 8; nt++)
            #pragma unroll
            for (int r = 0; r < 4; r++) { acch[mt][nt][r] = 0.0f; accl[mt][nt][r] = 0.0f; }

    const int laneR = lane & 15;
    const int laneC = (lane >> 4) * 16;       // 0 or 16 bytes

    unsigned rowA[2], xorA[2], rowB[4], xorB[4];
    #pragma unroll
    for (int mt = 0; mt < 2; mt++) {
        int row = wm * 32 + mt * 16 + laneR;
        rowA[mt] = row * 128; xorA[mt] = (row & 7) << 4;
    }
    #pragma unroll
    for (int nt2 = 0; nt2 < 4; nt2++) {
        int row = wn * 64 + nt2 * 16 + laneR;
        rowB[nt2] = 32768 + row * 128; xorB[nt2] = (row & 7) << 4;
    }

    load_stage(0, 0);
    load_stage(1, 1);

    for (int kb = 0; kb < NKBLK; kb++) {
        const int buf = kb % NSTAGE;
        if (kb < NKBLK - 1) asm volatile("cp.async.wait_group 1;" ::: "memory");
        else                asm volatile("cp.async.wait_group 0;" ::: "memory");
        __syncthreads();

        const unsigned so = sbase + buf * STG_BYTES;

        #pragma unroll
        for (int kc = 0; kc < 4; kc++) {
            const unsigned cofs = kc * 32 + laneC;

            unsigned ah[2][4], al[2][4], bh[4][4];
            #pragma unroll
            for (int mt = 0; mt < 2; mt++) {
                ldsm_x4(ah[mt], so + rowA[mt] + (cofs ^ xorA[mt]));
                ldsm_x4(al[mt], so + 16384 + rowA[mt] + (cofs ^ xorA[mt]));
            }
            #pragma unroll
            for (int nt2 = 0; nt2 < 4; nt2++)
                ldsm_x4(bh[nt2], so + rowB[nt2] + (cofs ^ xorB[nt2]));

            #pragma unroll
            for (int mt = 0; mt < 2; mt++)
                #pragma unroll
                for (int nt = 0; nt < 8; nt++)
                    mma_f16(acch[mt][nt], ah[mt], bh[nt >> 1][nt & 1], bh[nt >> 1][(nt & 1) + 2]);
            #pragma unroll
            for (int mt = 0; mt < 2; mt++)
                #pragma unroll
                for (int nt = 0; nt < 8; nt++)
                    mma_f16(accl[mt][nt], al[mt], bh[nt >> 1][nt & 1], bh[nt >> 1][(nt & 1) + 2]);
        }

        if (kb + 2 < NKBLK) load_stage(kb + 2, (kb + 2) % NSTAGE);
    }

    // epilogue: C = scale*(acc_h + acc_l/2048 + bias)
    #pragma unroll
    for (int mt = 0; mt < 2; mt++) {
        int r0 = m0 + wm * 32 + mt * 16 + (lane >> 2);
        int r1 = r0 + 8;
        #pragma unroll
        for (int nt = 0; nt < 8; nt++) {
            int col = n0 + wn * 64 + nt * 8 + 2 * (lane & 3);
            float2 bv = *(const float2*)&bias[col];
            float2 o0, o1;
            o0.x = scale * (acch[mt][nt][0] + accl[mt][nt][0] * INV_LO + bv.x);
            o0.y = scale * (acch[mt][nt][1] + accl[mt][nt][1] * INV_LO + bv.y);
            o1.x = scale * (acch[mt][nt][2] + accl[mt][nt][2] * INV_LO + bv.x);
            o1.y = scale * (acch[mt][nt][3] + accl[mt][nt][3] * INV_LO + bv.y);
            *(float2*)&C[(size_t)r0 * EMB + col] = o0;
            *(float2*)&C[(size_t)r1 * EMB + col] = o1;
        }
    }
}

// ---------------------------------------------------------------------------
// Axial attention core (fp32): one (batch, line, head) per block. 56 pos, D=64.
// ---------------------------------------------------------------------------
struct __align__(16) AttnSmem {
    float Qs[HH * DH];   // [y][d]; reused as P[56*56] after scores
    float Kt[DH * HH];   // [d][y] transposed
    float Vs[HH * DH];   // [y][d]
};

__device__ __forceinline__ void attn_core(
    const float* __restrict__ qg, int qstride,
    const float* __restrict__ kg,
    const float* __restrict__ vg, int vstride,
    float* __restrict__ og, int ostride,
    AttnSmem* sm)
{
    const int tid  = threadIdx.x;
    const int lane = tid & 31;
    const int warp = tid >> 5;

    for (int idx = tid; idx < HH * 16; idx += 256) {
        int y = idx >> 4;
        int j = (idx & 15) * 4;
        float4 q4 = *(const float4*)(qg + (size_t)y * qstride + j);
        *(float4*)&sm->Qs[y * DH + j] = q4;
        float4 k4 = *(const float4*)(kg + (size_t)y * qstride + j);
        sm->Kt[(j+0) * HH + y] = k4.x;
        sm->Kt[(j+1) * HH + y] = k4.y;
        sm->Kt[(j+2) * HH + y] = k4.z;
        sm->Kt[(j+3) * HH + y] = k4.w;
        float4 v4 = *(const float4*)(vg + (size_t)y * vstride + j);
        *(float4*)&sm->Vs[y * DH + j] = v4;
    }
    __syncthreads();

    const int  xbase = warp * 7;
    const int  y1    = lane + 32;
    const bool hasY1 = (y1 < HH);

    float acc0[7], acc1[7];
    #pragma unroll
    for (int xi = 0; xi < 7; xi++) { acc0[xi] = 0.0f; acc1[xi] = 0.0f; }

    #pragma unroll 1
    for (int d0 = 0; d0 < DH; d0 += 16) {
        float kr0[16], kr1[16];
        #pragma unroll
        for (int t = 0; t < 16; t++) {
            kr0[t] = sm->Kt[(d0+t) * HH + lane];
            kr1[t] = hasY1 ? sm->Kt[(d0+t) * HH + y1] : 0.0f;
        }
        #pragma unroll
        for (int xi = 0; xi < 7; xi++) {
            const float4* q4 = (const float4*)&sm->Qs[(xbase+xi) * DH + d0];
            #pragma unroll
            for (int t4 = 0; t4 < 4; t4++) {
                float4 qv = q4[t4];
                acc0[xi] = fmaf(qv.x, kr0[t4*4+0], acc0[xi]);
                acc0[xi] = fmaf(qv.y, kr0[t4*4+1], acc0[xi]);
                acc0[xi] = fmaf(qv.z, kr0[t4*4+2], acc0[xi]);
                acc0[xi] = fmaf(qv.w, kr0[t4*4+3], acc0[xi]);
                acc1[xi] = fmaf(qv.x, kr1[t4*4+0], acc1[xi]);
                acc1[xi] = fmaf(qv.y, kr1[t4*4+1], acc1[xi]);
                acc1[xi] = fmaf(qv.z, kr1[t4*4+2], acc1[xi]);
                acc1[xi] = fmaf(qv.w, kr1[t4*4+3], acc1[xi]);
            }
        }
    }

    #pragma unroll
    for (int xi = 0; xi < 7; xi++) {
        float m = acc0[xi];
        if (hasY1) m = fmaxf(m, acc1[xi]);
        #pragma unroll
        for (int off = 16; off > 0; off >>= 1)
            m = fmaxf(m, __shfl_xor_sync(0xffffffffu, m, off));
        float e0 = expf(acc0[xi] - m);
        float e1 = hasY1 ? expf(acc1[xi] - m) : 0.0f;
        float s = e0 + e1;
        #pragma unroll
        for (int off = 16; off > 0; off >>= 1)
            s += __shfl_xor_sync(0xffffffffu, s, off);
        float inv = 1.0f / s;
        acc0[xi] = e0 * inv;
        acc1[xi] = e1 * inv;
    }

    __syncthreads();
    float* P = sm->Qs;
    #pragma unroll
    for (int xi = 0; xi < 7; xi++) {
        P[(xbase+xi) * HH + lane] = acc0[xi];
        if (hasY1) P[(xbase+xi) * HH + y1] = acc1[xi];
    }
    __syncthreads();

    const int d1 = lane + 32;
    float o0[7], o1[7];
    #pragma unroll
    for (int xi = 0; xi < 7; xi++) { o0[xi] = 0.0f; o1[xi] = 0.0f; }

    #pragma unroll 1
    for (int y0 = 0; y0 < HH; y0 += 8) {
        float vr0[8], vr1[8];
        #pragma unroll
        for (int t = 0; t < 8; t++) {
            vr0[t] = sm->Vs[(y0+t) * DH + lane];
            vr1[t] = sm->Vs[(y0+t) * DH + d1];
        }
        #pragma unroll
        for (int xi = 0; xi < 7; xi++) {
            const float4* p4 = (const float4*)&P[(xbase+xi) * HH + y0];
            float4 pa = p4[0], pb = p4[1];
            o0[xi] = fmaf(pa.x, vr0[0], o0[xi]);
            o0[xi] = fmaf(pa.y, vr0[1], o0[xi]);
            o0[xi] = fmaf(pa.z, vr0[2], o0[xi]);
            o0[xi] = fmaf(pa.w, vr0[3], o0[xi]);
            o0[xi] = fmaf(pb.x, vr0[4], o0[xi]);
            o0[xi] = fmaf(pb.y, vr0[5], o0[xi]);
            o0[xi] = fmaf(pb.z, vr0[6], o0[xi]);
            o0[xi] = fmaf(pb.w, vr0[7], o0[xi]);
            o1[xi] = fmaf(pa.x, vr1[0], o1[xi]);
            o1[xi] = fmaf(pa.y, vr1[1], o1[xi]);
            o1[xi] = fmaf(pa.z, vr1[2], o1[xi]);
            o1[xi] = fmaf(pa.w, vr1[3], o1[xi]);
            o1[xi] = fmaf(pb.x, vr1[4], o1[xi]);
            o1[xi] = fmaf(pb.y, vr1[5], o1[xi]);
            o1[xi] = fmaf(pb.z, vr1[6], o1[xi]);
            o1[xi] = fmaf(pb.w, vr1[7], o1[xi]);
        }
    }

    #pragma unroll
    for (int xi = 0; xi < 7; xi++) {
        float* orow = og + (size_t)(xbase+xi) * ostride;
        orow[lane] = o0[xi];
        orow[d1]   = o1[xi];
    }
}

__global__ __launch_bounds__(256)
void attn_w_kernel(const float* __restrict__ q, const float* __restrict__ k,
                   const float* __restrict__ v, float* __restrict__ vw)
{
    __shared__ AttnSmem sm;
    const int n = blockIdx.x, h = blockIdx.y, b = blockIdx.z;
    size_t qoff = ((size_t)(b*HH + h) * WW) * EMB + n * DH;
    float* og = vw + ((size_t)((b*HH + h) * NH + n) * WW) * DH;
    attn_core(q + qoff, EMB, k + qoff, v + qoff, EMB, og, DH, &sm);
}

__global__ __launch_bounds__(256)
void attn_h_kernel(const float* __restrict__ q, const float* __restrict__ k,
                   const float* __restrict__ vw, float* __restrict__ out)
{
    __shared__ AttnSmem sm;
    const int n = blockIdx.x, w = blockIdx.y, b = blockIdx.z;
    size_t qoff = ((size_t)b * HH * WW + w) * EMB + n * DH;
    const float* vg = vw + ((size_t)(b*HH*NH + n) * WW + w) * DH;
    attn_core(q + qoff, WW*EMB, k + qoff, vg, NH*WW*DH, out + qoff, WW*EMB, &sm);
}

// ---------------------------------------------------------------------------
extern "C" void kernel_launch(void* const* d_in, const int* in_sizes, int n_in,
                              void* d_out, int out_size)
{
    const float* x  = (const float*)d_in[0];
    const float* Wq = (const float*)d_in[1];
    const float* bq = (const float*)d_in[2];
    const float* Wk = (const float*)d_in[3];
    const float* bk = (const float*)d_in[4];
    const float* Wv = (const float*)d_in[5];
    const float* bv = (const float*)d_in[6];
    const float* Wo = (const float*)d_in[7];
    const float* bo = (const float*)d_in[8];

    float *q, *k, *v, *vw, *ao;
    __half *xh, *xls, *aoh, *aols, *wh;
    cudaGetSymbolAddress((void**)&q,    g_q);
    cudaGetSymbolAddress((void**)&k,    g_k);
    cudaGetSymbolAddress((void**)&v,    g_v);
    cudaGetSymbolAddress((void**)&vw,   g_vw);
    cudaGetSymbolAddress((void**)&ao,   g_ao);
    cudaGetSymbolAddress((void**)&xh,   g_xh);
    cudaGetSymbolAddress((void**)&xls,  g_xls);
    cudaGetSymbolAddress((void**)&aoh,  g_aoh);
    cudaGetSymbolAddress((void**)&aols, g_aols);
    cudaGetSymbolAddress((void**)&wh,   g_wh);

    static bool attr_set = false;
    if (!attr_set) {
        cudaFuncSetAttribute(gemm_f16_2t,
                             cudaFuncAttributeMaxDynamicSharedMemorySize, GEMM_SMEM);
        attr_set = true;
    }

    const int WSZ = EMB * EMB;           // 589824
    const int XSZ = TOK * EMB;           // 38535168

    split_f32_f16s<<<XSZ/1024, 256>>>(x, xh, xls, XSZ);
    {
        dim3 gw(WSZ/1024, 1, 4);
        conv4_f16<<<gw, 256>>>(Wq, Wk, Wv, Wo, wh, WSZ);
    }

    dim3 gg(EMB/TN, TOK/TM);             // (6, 392) — N-tiles fastest for L2 A reuse
    gemm_f16_2t<<<gg, NTHREADS, GEMM_SMEM>>>(xh, xls, wh + 0*(size_t)WSZ, bq, q, 1.0f);
    gemm_f16_2t<<<gg, NTHREADS, GEMM_SMEM>>>(xh, xls, wh + 1*(size_t)WSZ, bk, k, SCALING);
    gemm_f16_2t<<<gg, NTHREADS, GEMM_SMEM>>>(xh, xls, wh + 2*(size_t)WSZ, bv, v, 1.0f);

    dim3 ga(NH, HH, BB);                 // (12, 56, 16)
    attn_w_kernel<<<ga, 256>>>(q, k, v, vw);
    attn_h_kernel<<<ga, 256>>>(q, k, vw, ao);

    split_f32_f16s<<<XSZ/1024, 256>>>(ao, aoh, aols, XSZ);
    gemm_f16_2t<<<gg, NTHREADS, GEMM_SMEM>>>(aoh, aols, wh + 3*(size_t)WSZ, bo,
                                             (float*)d_out, 1.0f);
}

// round 8
// speedup vs baseline: 1.7018x; 1.0890x over previous
#include <cuda_runtime.h>
#include <cuda_fp16.h>
#include <math.h>

#define BB 16
#define HH 56
#define WW 56
#define EMB 768
#define NH 12
#define DH 64
#define TOK (BB*HH*WW)          // 50176
#define SCALING 0.125f          // 64^-0.5
#define LO_SCALE 2048.0f
#define INV_LO   (1.0f/2048.0f)

// ---- GEMM tiling (mma.sync fp16 2-term; tcgen05 unavailable on compute_100) ----
#define TM 128
#define TN 96
#define BK 64
#define NKBLK (EMB/BK)          // 12
#define GEMM_NT 384             // 12 warps: 4 (M) x 3 (N), warp tile 32x32
#define STG_BYTES 45056         // Ah 16K + Al 16K + B 12K
#define NSTAGE 3
#define GEMM_SMEM (NSTAGE*STG_BYTES)   // 135168

// ---------------- scratch (static device arrays; no allocation) ----------------
__device__ float g_q [(size_t)TOK * EMB];
__device__ float g_k [(size_t)TOK * EMB];
__device__ float g_v [(size_t)TOK * EMB];
__device__ float g_vw[(size_t)TOK * EMB];
__device__ float g_ao[(size_t)TOK * EMB];

__device__ __half g_xh  [(size_t)TOK * EMB];
__device__ __half g_xls [(size_t)TOK * EMB];
__device__ __half g_aoh [(size_t)TOK * EMB];
__device__ __half g_aols[(size_t)TOK * EMB];
__device__ __half g_wh  [(size_t)4 * EMB * EMB];

// ---------------------------------------------------------------------------
__global__ void split_f32_f16s(const float* __restrict__ s,
                               __half* __restrict__ hi,
                               __half* __restrict__ los, int n)
{
    int i = (blockIdx.x * blockDim.x + threadIdx.x) * 4;
    if (i >= n) return;
    float4 v = *(const float4*)(s + i);
    __half h0 = __float2half_rn(v.x);
    __half h1 = __float2half_rn(v.y);
    __half h2 = __float2half_rn(v.z);
    __half h3 = __float2half_rn(v.w);
    __half l0 = __float2half_rn((v.x - __half2float(h0)) * LO_SCALE);
    __half l1 = __float2half_rn((v.y - __half2float(h1)) * LO_SCALE);
    __half l2 = __float2half_rn((v.z - __half2float(h2)) * LO_SCALE);
    __half l3 = __float2half_rn((v.w - __half2float(h3)) * LO_SCALE);
    *(__half2*)(hi + i)      = __halves2half2(h0, h1);
    *(__half2*)(hi + i + 2)  = __halves2half2(h2, h3);
    *(__half2*)(los + i)     = __halves2half2(l0, l1);
    *(__half2*)(los + i + 2) = __halves2half2(l2, l3);
}

__global__ void conv4_f16(const float* __restrict__ w0, const float* __restrict__ w1,
                          const float* __restrict__ w2, const float* __restrict__ w3,
                          __half* __restrict__ dst, int n)
{
    const float* src = (blockIdx.z == 0) ? w0 : (blockIdx.z == 1) ? w1
                     : (blockIdx.z == 2) ? w2 : w3;
    __half* d = dst + (size_t)blockIdx.z * n;
    int i = (blockIdx.x * blockDim.x + threadIdx.x) * 4;
    if (i >= n) return;
    float4 v = *(const float4*)(src + i);
    *(__half2*)(d + i)     = __halves2half2(__float2half_rn(v.x), __float2half_rn(v.y));
    *(__half2*)(d + i + 2) = __halves2half2(__float2half_rn(v.z), __float2half_rn(v.w));
}

// ---------------------------------------------------------------------------
__device__ __forceinline__ unsigned smem_u32(const void* p) {
    return (unsigned)__cvta_generic_to_shared(p);
}
__device__ __forceinline__ void cp16(unsigned dst, const void* src) {
    asm volatile("cp.async.cg.shared.global [%0], [%1], 16;" :: "r"(dst), "l"(src));
}
__device__ __forceinline__ void ldsm_x4(unsigned* r, unsigned addr) {
    asm volatile("ldmatrix.sync.aligned.m8n8.x4.shared.b16 {%0,%1,%2,%3}, [%4];"
                 : "=r"(r[0]), "=r"(r[1]), "=r"(r[2]), "=r"(r[3]) : "r"(addr));
}
__device__ __forceinline__ void mma_f16(float* c, const unsigned* a, unsigned b0, unsigned b1) {
    asm volatile("mma.sync.aligned.m16n8k16.row.col.f32.f16.f16.f32 "
                 "{%0,%1,%2,%3}, {%4,%5,%6,%7}, {%8,%9}, {%0,%1,%2,%3};"
                 : "+f"(c[0]), "+f"(c[1]), "+f"(c[2]), "+f"(c[3])
                 : "r"(a[0]), "r"(a[1]), "r"(a[2]), "r"(a[3]), "r"(b0), "r"(b1));
}
__device__ __forceinline__ void split2u(float x, float y, unsigned& hi, unsigned& lo) {
    __half hx = __float2half_rn(x), hy = __float2half_rn(y);
    __half lx = __float2half_rn((x - __half2float(hx)) * LO_SCALE);
    __half ly = __float2half_rn((y - __half2float(hy)) * LO_SCALE);
    __half2 h = __halves2half2(hx, hy), l = __halves2half2(lx, ly);
    hi = *(unsigned*)&h; lo = *(unsigned*)&l;
}

// ---------------------------------------------------------------------------
// fp16 2-term GEMM, 384 threads, tile 128x96, warp tile 32x32, BK=64, 3 stages.
// ---------------------------------------------------------------------------
__global__ __launch_bounds__(GEMM_NT, 1)
void gemm_f16_2t(const __half* __restrict__ Ah, const __half* __restrict__ Als,
                 const __half* __restrict__ Bh,
                 const float* __restrict__ bias, float* __restrict__ C, float scale)
{
    extern __shared__ __align__(1024) char smraw[];
    const unsigned sbase = smem_u32(smraw);

    const int tid  = threadIdx.x;
    const int lane = tid & 31;
    const int warp = tid >> 5;
    const int wm   = warp & 3;           // 0..3  (M 32-chunks)
    const int wn   = warp >> 2;          // 0..2  (N 32-chunks)
    const int m0   = blockIdx.y * TM;
    const int n0   = blockIdx.x * TN;

    auto load_stage = [&](int kb, int buf) {
        const unsigned so = sbase + buf * STG_BYTES;
        const int kofs = kb * BK;
        for (int i = tid; i < TM * 8; i += GEMM_NT) {
            int row = i >> 3, ch = i & 7;
            unsigned sw = (unsigned)((ch * 16) ^ ((row & 7) << 4));
            const size_t g = (size_t)(m0 + row) * EMB + kofs + ch * 8;
            cp16(so + row * 128 + sw, Ah + g);
            cp16(so + 16384 + row * 128 + sw, Als + g);
        }
        for (int i = tid; i < TN * 8; i += GEMM_NT) {
            int row = i >> 3, ch = i & 7;
            unsigned sw = (unsigned)((ch * 16) ^ ((row & 7) << 4));
            cp16(so + 32768 + row * 128 + sw,
                 Bh + (size_t)(n0 + row) * EMB + kofs + ch * 8);
        }
        asm volatile("cp.async.commit_group;" ::: "memory");
    };

    float acch[2][4][4], accl[2][4][4];
    #pragma unroll
    for (int mt = 0; mt < 2; mt++)
        #pragma unroll
        for (int nt = 0; nt < 4; nt++)
            #pragma unroll
            for (int r = 0; r < 4; r++) { acch[mt][nt][r] = 0.0f; accl[mt][nt][r] = 0.0f; }

    const int laneR = lane & 15;
    const int laneC = (lane >> 4) * 16;

    unsigned rowA[2], xorA[2], rowB[2], xorB[2];
    #pragma unroll
    for (int mt = 0; mt < 2; mt++) {
        int row = wm * 32 + mt * 16 + laneR;
        rowA[mt] = row * 128; xorA[mt] = (row & 7) << 4;
    }
    #pragma unroll
    for (int nt2 = 0; nt2 < 2; nt2++) {
        int row = wn * 32 + nt2 * 16 + laneR;
        rowB[nt2] = 32768 + row * 128; xorB[nt2] = (row & 7) << 4;
    }

    load_stage(0, 0);
    load_stage(1, 1);

    for (int kb = 0; kb < NKBLK; kb++) {
        const int buf = kb % NSTAGE;
        if (kb < NKBLK - 1) asm volatile("cp.async.wait_group 1;" ::: "memory");
        else                asm volatile("cp.async.wait_group 0;" ::: "memory");
        __syncthreads();

        const unsigned so = sbase + buf * STG_BYTES;

        #pragma unroll
        for (int kc = 0; kc < 4; kc++) {
            const unsigned cofs = kc * 32 + laneC;

            unsigned ah[2][4], al[2][4], bh[2][4];
            #pragma unroll
            for (int mt = 0; mt < 2; mt++) {
                ldsm_x4(ah[mt], so + rowA[mt] + (cofs ^ xorA[mt]));
                ldsm_x4(al[mt], so + 16384 + rowA[mt] + (cofs ^ xorA[mt]));
            }
            #pragma unroll
            for (int nt2 = 0; nt2 < 2; nt2++)
                ldsm_x4(bh[nt2], so + rowB[nt2] + (cofs ^ xorB[nt2]));

            #pragma unroll
            for (int mt = 0; mt < 2; mt++)
                #pragma unroll
                for (int nt = 0; nt < 4; nt++)
                    mma_f16(acch[mt][nt], ah[mt], bh[nt >> 1][nt & 1], bh[nt >> 1][(nt & 1) + 2]);
            #pragma unroll
            for (int mt = 0; mt < 2; mt++)
                #pragma unroll
                for (int nt = 0; nt < 4; nt++)
                    mma_f16(accl[mt][nt], al[mt], bh[nt >> 1][nt & 1], bh[nt >> 1][(nt & 1) + 2]);
        }

        if (kb + 2 < NKBLK) load_stage(kb + 2, (kb + 2) % NSTAGE);
    }

    #pragma unroll
    for (int mt = 0; mt < 2; mt++) {
        int r0 = m0 + wm * 32 + mt * 16 + (lane >> 2);
        int r1 = r0 + 8;
        #pragma unroll
        for (int nt = 0; nt < 4; nt++) {
            int col = n0 + wn * 32 + nt * 8 + 2 * (lane & 3);
            float2 bv = *(const float2*)&bias[col];
            float2 o0, o1;
            o0.x = scale * (acch[mt][nt][0] + accl[mt][nt][0] * INV_LO + bv.x);
            o0.y = scale * (acch[mt][nt][1] + accl[mt][nt][1] * INV_LO + bv.y);
            o1.x = scale * (acch[mt][nt][2] + accl[mt][nt][2] * INV_LO + bv.x);
            o1.y = scale * (acch[mt][nt][3] + accl[mt][nt][3] * INV_LO + bv.y);
            *(float2*)&C[(size_t)r0 * EMB + col] = o0;
            *(float2*)&C[(size_t)r1 * EMB + col] = o1;
        }
    }
}

// ---------------------------------------------------------------------------
// Tensor-core axial attention: one (batch, line, head) per 128-thread block.
// 56 positions padded to 64. Q,K single fp16 (logits ~0.03 -> err ~1e-5);
// softmax in C-fragment registers; P,V as 2-term fp16 (3-mma PV).
// ---------------------------------------------------------------------------
struct __align__(16) AttnSmemH {
    __half Qs[64*64];   // rows x, swizzled, 8K
    __half Ks[64*64];   // rows y, 8K
    __half Vh[64*64];   // rows d (transposed), cols y, 8K
    __half Vl[64*64];   // 8K
};

__device__ __forceinline__ void attn_mma(
    const float* __restrict__ qg, int qstride,
    const float* __restrict__ kg,
    const float* __restrict__ vg, int vstride,
    float* __restrict__ og, int ostride,
    AttnSmemH* sm)
{
    const int tid  = threadIdx.x;          // 0..127
    const int lane = tid & 31;
    const int warp = tid >> 5;             // 0..3

    // zero all smem (pad rows/cols must be 0, not garbage)
    {
        uint4* p = (uint4*)sm;
        #pragma unroll
        for (int i = 0; i < 16; i++)
            p[tid + i * 128] = make_uint4(0u, 0u, 0u, 0u);
    }
    __syncthreads();

    char* qb = (char*)sm->Qs;
    char* kb = (char*)sm->Ks;
    char* vhb = (char*)sm->Vh;
    char* vlb = (char*)sm->Vl;

    for (int u = tid; u < HH * 16; u += 128) {
        int y = u >> 4, j4 = (u & 15) * 4;
        float4 q4 = *(const float4*)(qg + (size_t)y * qstride + j4);
        unsigned qoff = y * 128 + (((unsigned)(j4 * 2)) ^ ((y & 7) << 4));
        *(__half2*)(qb + qoff)     = __halves2half2(__float2half_rn(q4.x), __float2half_rn(q4.y));
        *(__half2*)(qb + qoff + 4) = __halves2half2(__float2half_rn(q4.z), __float2half_rn(q4.w));
        float4 k4 = *(const float4*)(kg + (size_t)y * qstride + j4);
        *(__half2*)(kb + qoff)     = __halves2half2(__float2half_rn(k4.x), __float2half_rn(k4.y));
        *(__half2*)(kb + qoff + 4) = __halves2half2(__float2half_rn(k4.z), __float2half_rn(k4.w));
        float4 v4 = *(const float4*)(vg + (size_t)y * vstride + j4);
        float vv[4] = {v4.x, v4.y, v4.z, v4.w};
        #pragma unroll
        for (int t = 0; t < 4; t++) {
            int d = j4 + t;
            __half h = __float2half_rn(vv[t]);
            __half l = __float2half_rn((vv[t] - __half2float(h)) * LO_SCALE);
            unsigned off = d * 128 + (((unsigned)(y * 2)) ^ ((d & 7) << 4));
            *(__half*)(vhb + off) = h;
            *(__half*)(vlb + off) = l;
        }
    }
    __syncthreads();

    const int laneR = lane & 15;
    const int laneC = (lane >> 4) * 16;

    const unsigned qrow = warp * 16 + laneR;
    const unsigned qbase = smem_u32(sm->Qs) + qrow * 128;
    const unsigned qxor  = (qrow & 7) << 4;

    unsigned kbs[4], vhs[4], vls[4], bx[4];
    #pragma unroll
    for (int nt2 = 0; nt2 < 4; nt2++) {
        unsigned row = nt2 * 16 + laneR;
        kbs[nt2] = smem_u32(sm->Ks) + row * 128;
        vhs[nt2] = smem_u32(sm->Vh) + row * 128;
        vls[nt2] = smem_u32(sm->Vl) + row * 128;
        bx[nt2]  = (row & 7) << 4;
    }

    // ---- S = Q @ K^T ----
    float s_[8][4];
    #pragma unroll
    for (int nt = 0; nt < 8; nt++)
        #pragma unroll
        for (int r = 0; r < 4; r++) s_[nt][r] = 0.0f;

    #pragma unroll
    for (int kc = 0; kc < 4; kc++) {
        const unsigned cofs = kc * 32 + laneC;
        unsigned a[4];
        ldsm_x4(a, qbase + (cofs ^ qxor));
        #pragma unroll
        for (int nt2 = 0; nt2 < 4; nt2++) {
            unsigned b[4];
            ldsm_x4(b, kbs[nt2] + (cofs ^ bx[nt2]));
            mma_f16(s_[2*nt2+0], a, b[0], b[2]);
            mma_f16(s_[2*nt2+1], a, b[1], b[3]);
        }
    }

    // ---- softmax over cols (frags 0..6 valid; frag 7 = pad cols 56..63) ----
    float m0 = -1e30f, m1 = -1e30f;
    #pragma unroll
    for (int nt = 0; nt < 7; nt++) {
        m0 = fmaxf(m0, fmaxf(s_[nt][0], s_[nt][1]));
        m1 = fmaxf(m1, fmaxf(s_[nt][2], s_[nt][3]));
    }
    m0 = fmaxf(m0, __shfl_xor_sync(0xffffffffu, m0, 1));
    m0 = fmaxf(m0, __shfl_xor_sync(0xffffffffu, m0, 2));
    m1 = fmaxf(m1, __shfl_xor_sync(0xffffffffu, m1, 1));
    m1 = fmaxf(m1, __shfl_xor_sync(0xffffffffu, m1, 2));

    float sum0 = 0.0f, sum1 = 0.0f;
    #pragma unroll
    for (int nt = 0; nt < 7; nt++) {
        s_[nt][0] = __expf(s_[nt][0] - m0);
        s_[nt][1] = __expf(s_[nt][1] - m0);
        s_[nt][2] = __expf(s_[nt][2] - m1);
        s_[nt][3] = __expf(s_[nt][3] - m1);
        sum0 += s_[nt][0] + s_[nt][1];
        sum1 += s_[nt][2] + s_[nt][3];
    }
    sum0 += __shfl_xor_sync(0xffffffffu, sum0, 1);
    sum0 += __shfl_xor_sync(0xffffffffu, sum0, 2);
    sum1 += __shfl_xor_sync(0xffffffffu, sum1, 1);
    sum1 += __shfl_xor_sync(0xffffffffu, sum1, 2);
    const float inv0 = 1.0f / sum0;
    const float inv1 = 1.0f / sum1;

    // ---- repack P into A-fragments (hi + scaled lo) ----
    unsigned aPh[4][4], aPl[4][4];
    #pragma unroll
    for (int kc = 0; kc < 4; kc++) {
        int f0 = 2 * kc, f1 = 2 * kc + 1;
        split2u(s_[f0][0] * inv0, s_[f0][1] * inv0, aPh[kc][0], aPl[kc][0]);
        split2u(s_[f0][2] * inv1, s_[f0][3] * inv1, aPh[kc][1], aPl[kc][1]);
        if (f1 < 7) {
            split2u(s_[f1][0] * inv0, s_[f1][1] * inv0, aPh[kc][2], aPl[kc][2]);
            split2u(s_[f1][2] * inv1, s_[f1][3] * inv1, aPh[kc][3], aPl[kc][3]);
        } else {
            aPh[kc][2] = aPh[kc][3] = 0u;
            aPl[kc][2] = aPl[kc][3] = 0u;
        }
    }

    // ---- O = P @ V  (3-term: ph*vh + pl*vh + ph*vl) ----
    float o_[8][4], ol_[8][4];
    #pragma unroll
    for (int nt = 0; nt < 8; nt++)
        #pragma unroll
        for (int r = 0; r < 4; r++) { o_[nt][r] = 0.0f; ol_[nt][r] = 0.0f; }

    #pragma unroll
    for (int kc = 0; kc < 4; kc++) {
        const unsigned cofs = kc * 32 + laneC;
        #pragma unroll
        for (int nt2 = 0; nt2 < 4; nt2++) {
            unsigned bh2[4], bl2[4];
            ldsm_x4(bh2, vhs[nt2] + (cofs ^ bx[nt2]));
            ldsm_x4(bl2, vls[nt2] + (cofs ^ bx[nt2]));
            mma_f16(o_[2*nt2+0], aPh[kc], bh2[0], bh2[2]);
            mma_f16(o_[2*nt2+1], aPh[kc], bh2[1], bh2[3]);
            mma_f16(ol_[2*nt2+0], aPl[kc], bh2[0], bh2[2]);
            mma_f16(ol_[2*nt2+1], aPl[kc], bh2[1], bh2[3]);
            mma_f16(ol_[2*nt2+0], aPh[kc], bl2[0], bl2[2]);
            mma_f16(ol_[2*nt2+1], aPh[kc], bl2[1], bl2[3]);
        }
    }

    // ---- store rows < 56 ----
    const int r0 = warp * 16 + (lane >> 2);     // always <= 55
    const int r1 = r0 + 8;
    #pragma unroll
    for (int nt = 0; nt < 8; nt++) {
        int col = nt * 8 + 2 * (lane & 3);
        float2 v0;
        v0.x = o_[nt][0] + ol_[nt][0] * INV_LO;
        v0.y = o_[nt][1] + ol_[nt][1] * INV_LO;
        *(float2*)(og + (size_t)r0 * ostride + col) = v0;
        if (r1 < HH) {
            float2 v1;
            v1.x = o_[nt][2] + ol_[nt][2] * INV_LO;
            v1.y = o_[nt][3] + ol_[nt][3] * INV_LO;
            *(float2*)(og + (size_t)r1 * ostride + col) = v1;
        }
    }
}

__global__ __launch_bounds__(128)
void attn_w_kernel(const float* __restrict__ q, const float* __restrict__ k,
                   const float* __restrict__ v, float* __restrict__ vw)
{
    __shared__ AttnSmemH sm;
    const int n = blockIdx.x, h = blockIdx.y, b = blockIdx.z;
    size_t qoff = ((size_t)(b*HH + h) * WW) * EMB + n * DH;
    float* og = vw + ((size_t)((b*HH + h) * NH + n) * WW) * DH;
    attn_mma(q + qoff, EMB, k + qoff, v + qoff, EMB, og, DH, &sm);
}

__global__ __launch_bounds__(128)
void attn_h_kernel(const float* __restrict__ q, const float* __restrict__ k,
                   const float* __restrict__ vw, float* __restrict__ out)
{
    __shared__ AttnSmemH sm;
    const int n = blockIdx.x, w = blockIdx.y, b = blockIdx.z;
    size_t qoff = ((size_t)b * HH * WW + w) * EMB + n * DH;
    const float* vg = vw + ((size_t)(b*HH*NH + n) * WW + w) * DH;
    attn_mma(q + qoff, WW*EMB, k + qoff, vg, NH*WW*DH, out + qoff, WW*EMB, &sm);
}

// ---------------------------------------------------------------------------
extern "C" void kernel_launch(void* const* d_in, const int* in_sizes, int n_in,
                              void* d_out, int out_size)
{
    const float* x  = (const float*)d_in[0];
    const float* Wq = (const float*)d_in[1];
    const float* bq = (const float*)d_in[2];
    const float* Wk = (const float*)d_in[3];
    const float* bk = (const float*)d_in[4];
    const float* Wv = (const float*)d_in[5];
    const float* bv = (const float*)d_in[6];
    const float* Wo = (const float*)d_in[7];
    const float* bo = (const float*)d_in[8];

    float *q, *k, *v, *vw, *ao;
    __half *xh, *xls, *aoh, *aols, *wh;
    cudaGetSymbolAddress((void**)&q,    g_q);
    cudaGetSymbolAddress((void**)&k,    g_k);
    cudaGetSymbolAddress((void**)&v,    g_v);
    cudaGetSymbolAddress((void**)&vw,   g_vw);
    cudaGetSymbolAddress((void**)&ao,   g_ao);
    cudaGetSymbolAddress((void**)&xh,   g_xh);
    cudaGetSymbolAddress((void**)&xls,  g_xls);
    cudaGetSymbolAddress((void**)&aoh,  g_aoh);
    cudaGetSymbolAddress((void**)&aols, g_aols);
    cudaGetSymbolAddress((void**)&wh,   g_wh);

    static bool attr_set = false;
    if (!attr_set) {
        cudaFuncSetAttribute(gemm_f16_2t,
                             cudaFuncAttributeMaxDynamicSharedMemorySize, GEMM_SMEM);
        attr_set = true;
    }

    const int WSZ = EMB * EMB;           // 589824
    const int XSZ = TOK * EMB;           // 38535168

    split_f32_f16s<<<XSZ/1024, 256>>>(x, xh, xls, XSZ);
    {
        dim3 gw(WSZ/1024, 1, 4);
        conv4_f16<<<gw, 256>>>(Wq, Wk, Wv, Wo, wh, WSZ);
    }

    dim3 gg(EMB/TN, TOK/TM);             // (8, 392) — N-tiles fastest for L2 A reuse
    gemm_f16_2t<<<gg, GEMM_NT, GEMM_SMEM>>>(xh, xls, wh + 0*(size_t)WSZ, bq, q, 1.0f);
    gemm_f16_2t<<<gg, GEMM_NT, GEMM_SMEM>>>(xh, xls, wh + 1*(size_t)WSZ, bk, k, SCALING);
    gemm_f16_2t<<<gg, GEMM_NT, GEMM_SMEM>>>(xh, xls, wh + 2*(size_t)WSZ, bv, v, 1.0f);

    dim3 ga(NH, HH, BB);                 // (12, 56, 16)
    attn_w_kernel<<<ga, 128>>>(q, k, v, vw);
    attn_h_kernel<<<ga, 128>>>(q, k, vw, ao);

    split_f32_f16s<<<XSZ/1024, 256>>>(ao, aoh, aols, XSZ);
    gemm_f16_2t<<<gg, GEMM_NT, GEMM_SMEM>>>(aoh, aols, wh + 3*(size_t)WSZ, bo,
                                            (float*)d_out, 1.0f);
}

// round 9
// speedup vs baseline: 3.1149x; 1.8304x over previous
#include <cuda_runtime.h>
#include <cuda_fp16.h>
#include <math.h>

#define BB 16
#define HH 56
#define WW 56
#define EMB 768
#define NH 12
#define DH 64
#define TOK (BB*HH*WW)          // 50176
#define QKVS (3*EMB)            // 2304
#define SCALING 0.125f          // 64^-0.5
#define LO_SCALE 2048.0f
#define INV_LO   (1.0f/2048.0f)

// ---- GEMM tiling (single-term fp16 mma.sync; tcgen05 unavailable on compute_100) ----
#define TM 128
#define TN 128
#define BK 64
#define NKBLK (EMB/BK)          // 12
#define GEMM_NT 256             // 8 warps: 4 (M) x 2 (N), warp tile 32x64
#define STG_BYTES 32768         // A 16K + B 16K
#define NSTAGE 3
#define GEMM_SMEM (NSTAGE*STG_BYTES)   // 98304

// ---------------- scratch (static device arrays; no allocation) ----------------
__device__ float g_qkv[(size_t)TOK * QKVS];      // fused q|k|v, 462MB
__device__ float g_vw [(size_t)TOK * EMB];
__device__ float g_ao [(size_t)TOK * EMB];
__device__ float g_bqkv[QKVS];

__device__ __half g_xh [(size_t)TOK * EMB];
__device__ __half g_aoh[(size_t)TOK * EMB];
__device__ __half g_wh [(size_t)4 * EMB * EMB];  // Wq | Wk*0.125 | Wv | Wo

// ---------------------------------------------------------------------------
__global__ void conv_f16(const float* __restrict__ s, __half* __restrict__ d, int n)
{
    int i = (blockIdx.x * blockDim.x + threadIdx.x) * 4;
    if (i >= n) return;
    float4 v = *(const float4*)(s + i);
    *(__half2*)(d + i)     = __halves2half2(__float2half_rn(v.x), __float2half_rn(v.y));
    *(__half2*)(d + i + 2) = __halves2half2(__float2half_rn(v.z), __float2half_rn(v.w));
}

__global__ void convw_f16(const float* __restrict__ w0, const float* __restrict__ w1,
                          const float* __restrict__ w2, const float* __restrict__ w3,
                          __half* __restrict__ dst, int n)
{
    int z = blockIdx.z;
    const float* src = (z == 0) ? w0 : (z == 1) ? w1 : (z == 2) ? w2 : w3;
    float sc = (z == 1) ? SCALING : 1.0f;
    __half* d = dst + (size_t)z * n;
    int i = (blockIdx.x * blockDim.x + threadIdx.x) * 4;
    if (i >= n) return;
    float4 v = *(const float4*)(src + i);
    *(__half2*)(d + i)     = __halves2half2(__float2half_rn(v.x*sc), __float2half_rn(v.y*sc));
    *(__half2*)(d + i + 2) = __halves2half2(__float2half_rn(v.z*sc), __float2half_rn(v.w*sc));
}

__global__ void bias_qkv_build(const float* __restrict__ bq, const float* __restrict__ bk,
                               const float* __restrict__ bv, float* __restrict__ dst)
{
    int i = blockIdx.x * blockDim.x + threadIdx.x;
    if (i >= QKVS) return;
    dst[i] = (i < EMB) ? bq[i] : (i < 2*EMB) ? bk[i - EMB] * SCALING : bv[i - 2*EMB];
}

// ---------------------------------------------------------------------------
__device__ __forceinline__ unsigned smem_u32(const void* p) {
    return (unsigned)__cvta_generic_to_shared(p);
}
__device__ __forceinline__ void cp16(unsigned dst, const void* src) {
    asm volatile("cp.async.cg.shared.global [%0], [%1], 16;" :: "r"(dst), "l"(src));
}
__device__ __forceinline__ void ldsm_x4(unsigned* r, unsigned addr) {
    asm volatile("ldmatrix.sync.aligned.m8n8.x4.shared.b16 {%0,%1,%2,%3}, [%4];"
                 : "=r"(r[0]), "=r"(r[1]), "=r"(r[2]), "=r"(r[3]) : "r"(addr));
}
__device__ __forceinline__ void mma_f16(float* c, const unsigned* a, unsigned b0, unsigned b1) {
    asm volatile("mma.sync.aligned.m16n8k16.row.col.f32.f16.f16.f32 "
                 "{%0,%1,%2,%3}, {%4,%5,%6,%7}, {%8,%9}, {%0,%1,%2,%3};"
                 : "+f"(c[0]), "+f"(c[1]), "+f"(c[2]), "+f"(c[3])
                 : "r"(a[0]), "r"(a[1]), "r"(a[2]), "r"(a[3]), "r"(b0), "r"(b1));
}
__device__ __forceinline__ void split2u(float x, float y, unsigned& hi, unsigned& lo) {
    __half hx = __float2half_rn(x), hy = __float2half_rn(y);
    __half lx = __float2half_rn((x - __half2float(hx)) * LO_SCALE);
    __half ly = __float2half_rn((y - __half2float(hy)) * LO_SCALE);
    __half2 h = __halves2half2(hx, hy), l = __halves2half2(lx, ly);
    hi = *(unsigned*)&h; lo = *(unsigned*)&l;
}

// ---------------------------------------------------------------------------
// Single-term fp16 GEMM: C[m, n] = A[m,:]·B[n,:] + bias[n]
// Tile 128x128, warp 32x64, BK=64, 3-stage cp.async, 256 threads, 2 CTAs/SM.
// ---------------------------------------------------------------------------
__global__ __launch_bounds__(GEMM_NT, 2)
void gemm_f16_1t(const __half* __restrict__ Ah, const __half* __restrict__ Bh,
                 const float* __restrict__ bias, float* __restrict__ C,
                 int N, int ldc)
{
    extern __shared__ __align__(1024) char smraw[];
    const unsigned sbase = smem_u32(smraw);

    const int tid  = threadIdx.x;
    const int lane = tid & 31;
    const int warp = tid >> 5;
    const int wm   = warp & 3;           // 0..3  (M 32-chunks)
    const int wn   = warp >> 2;          // 0..1  (N 64-chunks)
    const int m0   = blockIdx.y * TM;
    const int n0   = blockIdx.x * TN;

    auto load_stage = [&](int kb, int buf) {
        const unsigned so = sbase + buf * STG_BYTES;
        const int kofs = kb * BK;
        #pragma unroll
        for (int it = 0; it < 4; it++) {
            int i = tid + it * GEMM_NT;
            int row = i >> 3, ch = i & 7;
            unsigned sw = (unsigned)((ch * 16) ^ ((row & 7) << 4));
            cp16(so + row * 128 + sw,
                 Ah + (size_t)(m0 + row) * EMB + kofs + ch * 8);
        }
        #pragma unroll
        for (int it = 0; it < 4; it++) {
            int i = tid + it * GEMM_NT;
            int row = i >> 3, ch = i & 7;
            unsigned sw = (unsigned)((ch * 16) ^ ((row & 7) << 4));
            cp16(so + 16384 + row * 128 + sw,
                 Bh + (size_t)(n0 + row) * EMB + kofs + ch * 8);
        }
        asm volatile("cp.async.commit_group;" ::: "memory");
    };

    float acc[2][8][4];
    #pragma unroll
    for (int mt = 0; mt < 2; mt++)
        #pragma unroll
        for (int nt = 0; nt < 8; nt++)
            #pragma unroll
            for (int r = 0; r < 4; r++) acc[mt][nt][r] = 0.0f;

    const int laneR = lane & 15;
    const int laneC = (lane >> 4) * 16;

    unsigned rowA[2], xorA[2], rowB[4], xorB[4];
    #pragma unroll
    for (int mt = 0; mt < 2; mt++) {
        int row = wm * 32 + mt * 16 + laneR;
        rowA[mt] = row * 128; xorA[mt] = (row & 7) << 4;
    }
    #pragma unroll
    for (int nt2 = 0; nt2 < 4; nt2++) {
        int row = wn * 64 + nt2 * 16 + laneR;
        rowB[nt2] = 16384 + row * 128; xorB[nt2] = (row & 7) << 4;
    }

    load_stage(0, 0);
    load_stage(1, 1);

    for (int kb = 0; kb < NKBLK; kb++) {
        const int buf = kb % NSTAGE;
        if (kb < NKBLK - 1) asm volatile("cp.async.wait_group 1;" ::: "memory");
        else                asm volatile("cp.async.wait_group 0;" ::: "memory");
        __syncthreads();

        const unsigned so = sbase + buf * STG_BYTES;

        #pragma unroll
        for (int kc = 0; kc < 4; kc++) {
            const unsigned cofs = kc * 32 + laneC;

            unsigned ah[2][4], bh[4][4];
            #pragma unroll
            for (int mt = 0; mt < 2; mt++)
                ldsm_x4(ah[mt], so + rowA[mt] + (cofs ^ xorA[mt]));
            #pragma unroll
            for (int nt2 = 0; nt2 < 4; nt2++)
                ldsm_x4(bh[nt2], so + rowB[nt2] + (cofs ^ xorB[nt2]));

            #pragma unroll
            for (int mt = 0; mt < 2; mt++)
                #pragma unroll
                for (int nt = 0; nt < 8; nt++)
                    mma_f16(acc[mt][nt], ah[mt], bh[nt >> 1][nt & 1], bh[nt >> 1][(nt & 1) + 2]);
        }

        if (kb + 2 < NKBLK) load_stage(kb + 2, (kb + 2) % NSTAGE);
    }

    #pragma unroll
    for (int mt = 0; mt < 2; mt++) {
        int r0 = m0 + wm * 32 + mt * 16 + (lane >> 2);
        int r1 = r0 + 8;
        #pragma unroll
        for (int nt = 0; nt < 8; nt++) {
            int col = n0 + wn * 64 + nt * 8 + 2 * (lane & 3);
            float2 bv = *(const float2*)&bias[col];
            float2 o0, o1;
            o0.x = acc[mt][nt][0] + bv.x;
            o0.y = acc[mt][nt][1] + bv.y;
            o1.x = acc[mt][nt][2] + bv.x;
            o1.y = acc[mt][nt][3] + bv.y;
            *(float2*)&C[(size_t)r0 * ldc + col] = o0;
            *(float2*)&C[(size_t)r1 * ldc + col] = o1;
        }
    }
}

// ---------------------------------------------------------------------------
// Tensor-core axial attention (unchanged from R8-passing version; strides adapted).
// ---------------------------------------------------------------------------
struct __align__(16) AttnSmemH {
    __half Qs[64*64];
    __half Ks[64*64];
    __half Vh[64*64];   // d-major (transposed)
    __half Vl[64*64];
};

__device__ __forceinline__ void attn_mma(
    const float* __restrict__ qg, int qstride,
    const float* __restrict__ kg,
    const float* __restrict__ vg, int vstride,
    float* __restrict__ og, int ostride,
    AttnSmemH* sm)
{
    const int tid  = threadIdx.x;          // 0..127
    const int lane = tid & 31;
    const int warp = tid >> 5;             // 0..3

    // zero all smem (pad rows/cols must be 0)
    {
        uint4* p = (uint4*)sm;
        #pragma unroll
        for (int i = 0; i < 16; i++)
            p[tid + i * 128] = make_uint4(0u, 0u, 0u, 0u);
    }
    __syncthreads();

    char* qb = (char*)sm->Qs;
    char* kb = (char*)sm->Ks;
    char* vhb = (char*)sm->Vh;
    char* vlb = (char*)sm->Vl;

    for (int u = tid; u < HH * 16; u += 128) {
        int y = u >> 4, j4 = (u & 15) * 4;
        float4 q4 = *(const float4*)(qg + (size_t)y * qstride + j4);
        unsigned qoff = y * 128 + (((unsigned)(j4 * 2)) ^ ((y & 7) << 4));
        *(__half2*)(qb + qoff)     = __halves2half2(__float2half_rn(q4.x), __float2half_rn(q4.y));
        *(__half2*)(qb + qoff + 4) = __halves2half2(__float2half_rn(q4.z), __float2half_rn(q4.w));
        float4 k4 = *(const float4*)(kg + (size_t)y * qstride + j4);
        *(__half2*)(kb + qoff)     = __halves2half2(__float2half_rn(k4.x), __float2half_rn(k4.y));
        *(__half2*)(kb + qoff + 4) = __halves2half2(__float2half_rn(k4.z), __float2half_rn(k4.w));
        float4 v4 = *(const float4*)(vg + (size_t)y * vstride + j4);
        float vv[4] = {v4.x, v4.y, v4.z, v4.w};
        #pragma unroll
        for (int t = 0; t < 4; t++) {
            int d = j4 + t;
            __half h = __float2half_rn(vv[t]);
            __half l = __float2half_rn((vv[t] - __half2float(h)) * LO_SCALE);
            unsigned off = d * 128 + (((unsigned)(y * 2)) ^ ((d & 7) << 4));
            *(__half*)(vhb + off) = h;
            *(__half*)(vlb + off) = l;
        }
    }
    __syncthreads();

    const int laneR = lane & 15;
    const int laneC = (lane >> 4) * 16;

    const unsigned qrow = warp * 16 + laneR;
    const unsigned qbase = smem_u32(sm->Qs) + qrow * 128;
    const unsigned qxor  = (qrow & 7) << 4;

    unsigned kbs[4], vhs[4], vls[4], bx[4];
    #pragma unroll
    for (int nt2 = 0; nt2 < 4; nt2++) {
        unsigned row = nt2 * 16 + laneR;
        kbs[nt2] = smem_u32(sm->Ks) + row * 128;
        vhs[nt2] = smem_u32(sm->Vh) + row * 128;
        vls[nt2] = smem_u32(sm->Vl) + row * 128;
        bx[nt2]  = (row & 7) << 4;
    }

    // ---- S = Q @ K^T ----
    float s_[8][4];
    #pragma unroll
    for (int nt = 0; nt < 8; nt++)
        #pragma unroll
        for (int r = 0; r < 4; r++) s_[nt][r] = 0.0f;

    #pragma unroll
    for (int kc = 0; kc < 4; kc++) {
        const unsigned cofs = kc * 32 + laneC;
        unsigned a[4];
        ldsm_x4(a, qbase + (cofs ^ qxor));
        #pragma unroll
        for (int nt2 = 0; nt2 < 4; nt2++) {
            unsigned b[4];
            ldsm_x4(b, kbs[nt2] + (cofs ^ bx[nt2]));
            mma_f16(s_[2*nt2+0], a, b[0], b[2]);
            mma_f16(s_[2*nt2+1], a, b[1], b[3]);
        }
    }

    // ---- softmax over cols (frags 0..6 valid; frag 7 = pad cols) ----
    float m0 = -1e30f, m1 = -1e30f;
    #pragma unroll
    for (int nt = 0; nt < 7; nt++) {
        m0 = fmaxf(m0, fmaxf(s_[nt][0], s_[nt][1]));
        m1 = fmaxf(m1, fmaxf(s_[nt][2], s_[nt][3]));
    }
    m0 = fmaxf(m0, __shfl_xor_sync(0xffffffffu, m0, 1));
    m0 = fmaxf(m0, __shfl_xor_sync(0xffffffffu, m0, 2));
    m1 = fmaxf(m1, __shfl_xor_sync(0xffffffffu, m1, 1));
    m1 = fmaxf(m1, __shfl_xor_sync(0xffffffffu, m1, 2));

    float sum0 = 0.0f, sum1 = 0.0f;
    #pragma unroll
    for (int nt = 0; nt < 7; nt++) {
        s_[nt][0] = __expf(s_[nt][0] - m0);
        s_[nt][1] = __expf(s_[nt][1] - m0);
        s_[nt][2] = __expf(s_[nt][2] - m1);
        s_[nt][3] = __expf(s_[nt][3] - m1);
        sum0 += s_[nt][0] + s_[nt][1];
        sum1 += s_[nt][2] + s_[nt][3];
    }
    sum0 += __shfl_xor_sync(0xffffffffu, sum0, 1);
    sum0 += __shfl_xor_sync(0xffffffffu, sum0, 2);
    sum1 += __shfl_xor_sync(0xffffffffu, sum1, 1);
    sum1 += __shfl_xor_sync(0xffffffffu, sum1, 2);
    const float inv0 = 1.0f / sum0;
    const float inv1 = 1.0f / sum1;

    // ---- repack P into A-fragments (hi + scaled lo) ----
    unsigned aPh[4][4], aPl[4][4];
    #pragma unroll
    for (int kc = 0; kc < 4; kc++) {
        int f0 = 2 * kc, f1 = 2 * kc + 1;
        split2u(s_[f0][0] * inv0, s_[f0][1] * inv0, aPh[kc][0], aPl[kc][0]);
        split2u(s_[f0][2] * inv1, s_[f0][3] * inv1, aPh[kc][1], aPl[kc][1]);
        if (f1 < 7) {
            split2u(s_[f1][0] * inv0, s_[f1][1] * inv0, aPh[kc][2], aPl[kc][2]);
            split2u(s_[f1][2] * inv1, s_[f1][3] * inv1, aPh[kc][3], aPl[kc][3]);
        } else {
            aPh[kc][2] = aPh[kc][3] = 0u;
            aPl[kc][2] = aPl[kc][3] = 0u;
        }
    }

    // ---- O = P @ V  (ph*vh + pl*vh + ph*vl) ----
    float o_[8][4], ol_[8][4];
    #pragma unroll
    for (int nt = 0; nt < 8; nt++)
        #pragma unroll
        for (int r = 0; r < 4; r++) { o_[nt][r] = 0.0f; ol_[nt][r] = 0.0f; }

    #pragma unroll
    for (int kc = 0; kc < 4; kc++) {
        const unsigned cofs = kc * 32 + laneC;
        #pragma unroll
        for (int nt2 = 0; nt2 < 4; nt2++) {
            unsigned bh2[4], bl2[4];
            ldsm_x4(bh2, vhs[nt2] + (cofs ^ bx[nt2]));
            ldsm_x4(bl2, vls[nt2] + (cofs ^ bx[nt2]));
            mma_f16(o_[2*nt2+0], aPh[kc], bh2[0], bh2[2]);
            mma_f16(o_[2*nt2+1], aPh[kc], bh2[1], bh2[3]);
            mma_f16(ol_[2*nt2+0], aPl[kc], bh2[0], bh2[2]);
            mma_f16(ol_[2*nt2+1], aPl[kc], bh2[1], bh2[3]);
            mma_f16(ol_[2*nt2+0], aPh[kc], bl2[0], bl2[2]);
            mma_f16(ol_[2*nt2+1], aPh[kc], bl2[1], bl2[3]);
        }
    }

    // ---- store rows < 56 ----
    const int r0 = warp * 16 + (lane >> 2);
    const int r1 = r0 + 8;
    #pragma unroll
    for (int nt = 0; nt < 8; nt++) {
        int col = nt * 8 + 2 * (lane & 3);
        float2 v0;
        v0.x = o_[nt][0] + ol_[nt][0] * INV_LO;
        v0.y = o_[nt][1] + ol_[nt][1] * INV_LO;
        *(float2*)(og + (size_t)r0 * ostride + col) = v0;
        if (r1 < HH) {
            float2 v1;
            v1.x = o_[nt][2] + ol_[nt][2] * INV_LO;
            v1.y = o_[nt][3] + ol_[nt][3] * INV_LO;
            *(float2*)(og + (size_t)r1 * ostride + col) = v1;
        }
    }
}

__global__ __launch_bounds__(128)
void attn_w_kernel(const float* __restrict__ qkv, float* __restrict__ vw)
{
    __shared__ AttnSmemH sm;
    const int n = blockIdx.x, h = blockIdx.y, b = blockIdx.z;
    size_t base = ((size_t)(b*HH + h) * WW) * QKVS + n * DH;
    float* og = vw + ((size_t)((b*HH + h) * NH + n) * WW) * DH;
    attn_mma(qkv + base, QKVS, qkv + base + EMB, qkv + base + 2*EMB, QKVS, og, DH, &sm);
}

__global__ __launch_bounds__(128)
void attn_h_kernel(const float* __restrict__ qkv, const float* __restrict__ vw,
                   float* __restrict__ out)
{
    __shared__ AttnSmemH sm;
    const int n = blockIdx.x, w = blockIdx.y, b = blockIdx.z;
    size_t qoff = ((size_t)b * HH * WW + w) * QKVS + n * DH;
    const float* vg = vw + ((size_t)(b*HH*NH + n) * WW + w) * DH;
    float* og = out + ((size_t)b * HH * WW + w) * EMB + n * DH;
    attn_mma(qkv + qoff, WW*QKVS, qkv + qoff + EMB, vg, NH*WW*DH, og, WW*EMB, &sm);
}

// ---------------------------------------------------------------------------
extern "C" void kernel_launch(void* const* d_in, const int* in_sizes, int n_in,
                              void* d_out, int out_size)
{
    const float* x  = (const float*)d_in[0];
    const float* Wq = (const float*)d_in[1];
    const float* bq = (const float*)d_in[2];
    const float* Wk = (const float*)d_in[3];
    const float* bk = (const float*)d_in[4];
    const float* Wv = (const float*)d_in[5];
    const float* bv = (const float*)d_in[6];
    const float* Wo = (const float*)d_in[7];
    const float* bo = (const float*)d_in[8];

    float *qkv, *vw, *ao, *bqkv;
    __half *xh, *aoh, *wh;
    cudaGetSymbolAddress((void**)&qkv,  g_qkv);
    cudaGetSymbolAddress((void**)&vw,   g_vw);
    cudaGetSymbolAddress((void**)&ao,   g_ao);
    cudaGetSymbolAddress((void**)&bqkv, g_bqkv);
    cudaGetSymbolAddress((void**)&xh,   g_xh);
    cudaGetSymbolAddress((void**)&aoh,  g_aoh);
    cudaGetSymbolAddress((void**)&wh,   g_wh);

    static bool attr_set = false;
    if (!attr_set) {
        cudaFuncSetAttribute(gemm_f16_1t,
                             cudaFuncAttributeMaxDynamicSharedMemorySize, GEMM_SMEM);
        attr_set = true;
    }

    const int WSZ = EMB * EMB;           // 589824
    const int XSZ = TOK * EMB;           // 38535168

    conv_f16<<<XSZ/1024, 256>>>(x, xh, XSZ);
    {
        dim3 gw(WSZ/1024, 1, 4);
        convw_f16<<<gw, 256>>>(Wq, Wk, Wv, Wo, wh, WSZ);
    }
    bias_qkv_build<<<QKVS/256, 256>>>(bq, bk, bv, bqkv);

    // fused QKV projection: [TOK, 2304]
    {
        dim3 gg(QKVS/TN, TOK/TM);        // (18, 392)
        gemm_f16_1t<<<gg, GEMM_NT, GEMM_SMEM>>>(xh, wh, bqkv, qkv, QKVS, QKVS);
    }

    dim3 ga(NH, HH, BB);                 // (12, 56, 16)
    attn_w_kernel<<<ga, 128>>>(qkv, vw);
    attn_h_kernel<<<ga, 128>>>(qkv, vw, ao);

    conv_f16<<<XSZ/1024, 256>>>(ao, aoh, XSZ);
    {
        dim3 gg(EMB/TN, TOK/TM);         // (6, 392)
        gemm_f16_1t<<<gg, GEMM_NT, GEMM_SMEM>>>(aoh, wh + 3*(size_t)WSZ, bo,
                                                (float*)d_out, EMB, EMB);
    }
}